// round 14
// baseline (speedup 1.0000x reference)
#include <cuda_runtime.h>
#include <cstdint>
#include <math.h>

#define BB 8
#define CC 64
#define H2 128
#define W2 128
#define PX (H2*W2)          // 16384
#define NSUB (BB*CC*PX)     // 8388608

// conv3x3 smem image: [ci][18 rows][40 cols], col c <-> gx = tx*32-4+c
#define ROW_STR 40
#define CI_STR 728          // 18*40=720 padded to 728 (mod 32 = 24 -> tg banks {0,24,16,8})
#define IMG3 5824           // 8 * CI_STR
#define WCH3 4608           // weights per chunk: 9*64*8
#define BUF3 (IMG3 + WCH3)  // 10432 words per buffer

#define IN1_STR 264
#define W_STR 72
#define BUF1 5376

#define W3_GROUP 36864      // 8 chunks * 4608
#define W1_H2_OFF 0
#define W1_QKV_OFF 9216
#define W1_PROJ_OFF 13824

// ---------------- scratch (device globals; no runtime allocation) -----------
__device__ float g_ll[NSUB];
__device__ float g_lh[NSUB];
__device__ float g_hl[NSUB];
__device__ float g_hh[NSUB];
__device__ float g_h1[2*NSUB];
__device__ float g_filt[NSUB];
__device__ float g_t[NSUB];
__device__ float g_z[NSUB];
__device__ float g_yh[3*NSUB];
__device__ float g_w3[5*W3_GROUP];
__device__ float g_w1[18432];

// ---------------- helpers ----------------------------------------------------
__device__ __forceinline__ unsigned f2tf(float f) {
    unsigned u;
    asm("cvt.rna.tf32.f32 %0, %1;" : "=r"(u) : "f"(f));
    return u;
}
__device__ __forceinline__ float tf32r(float f) { return __uint_as_float(f2tf(f)); }

#define MMA_TF32(c0,c1,c2,c3,a0,a1,a2,a3,b0,b1)                                \
    asm volatile("mma.sync.aligned.m16n8k8.row.col.f32.tf32.tf32.f32 "          \
        "{%0,%1,%2,%3}, {%4,%5,%6,%7}, {%8,%9}, {%0,%1,%2,%3};\n"               \
        : "+f"(c0), "+f"(c1), "+f"(c2), "+f"(c3)                                \
        : "r"(a0), "r"(a1), "r"(a2), "r"(a3), "r"(b0), "r"(b1))

#define CP16(dst, src) \
    asm volatile("cp.async.ca.shared.global [%0], [%1], 16;\n" :: "r"(dst), "l"(src))
#define CP16Z(dst, src, sz) \
    asm volatile("cp.async.ca.shared.global [%0], [%1], 16, %2;\n" :: "r"(dst), "l"(src), "r"(sz))
#define CP_COMMIT()  asm volatile("cp.async.commit_group;\n")
#define CP_WAIT0()   asm volatile("cp.async.wait_group 0;\n" ::: "memory")

// ---------------- weight prep ------------------------------------------------
// 3x3 layout per group/chunk: word = (d*64 + o)*8 + 2*slot + par
//   slot = ((ci&3) + (o>>2)) & 3, par = ci>>2   (ci = in-chunk channel 0..7)
__global__ void k_prepw(const float* __restrict__ w_high1,
                        const float* __restrict__ w_highout,
                        const float* __restrict__ w_high2,
                        const float* __restrict__ w_qkv,
                        const float* __restrict__ w_proj) {
    int idx = blockIdx.x * 256 + threadIdx.x;
    const int total3 = 5 * W3_GROUP;   // 184320
    if (idx < total3) {
        int g = idx / W3_GROUP, r = idx - g * W3_GROUP;
        int ch = r / WCH3;  int w = r - ch * WCH3;
        int d = w / 512;    int rem = w - d * 512;
        int o = rem >> 3;   int s = rem & 7;
        int slot = s >> 1, par = s & 1;
        int ci = par * 4 + ((slot - (o >> 2)) & 3);
        const float* src = (g < 2) ? (w_high1 + g * 36864)
                                   : (w_highout + (g - 2) * 36864);
        float v = src[((size_t)o * 64 + ch * 8 + ci) * 9 + d];
        g_w3[idx] = tf32r(v);
    }
    int i1 = idx - total3;
    if (i1 >= 0 && i1 < 18432) {
        float v = 0.f;
        if (i1 < 9216) {               // high2: KC=128
            int ch = i1 / 1152, r = i1 - ch * 1152;
            int ci = r / 72, o = r - ci * 72;
            if (o < 64) v = w_high2[(size_t)o * 128 + ch * 16 + ci];
        } else if (i1 < 13824) {       // qkv v-slice: KC=64
            int r2 = i1 - 9216;
            int ch = r2 / 1152, r = r2 - ch * 1152;
            int ci = r / 72, o = r - ci * 72;
            if (o < 64) v = w_qkv[128 * 64 + (size_t)o * 64 + ch * 16 + ci];
        } else {                       // proj: KC=64
            int r2 = i1 - 13824;
            int ch = r2 / 1152, r = r2 - ch * 1152;
            int ci = r / 72, o = r - ci * 72;
            if (o < 64) v = w_proj[(size_t)o * 64 + ch * 16 + ci];
        }
        g_w1[i1] = tf32r(v);
    }
}

// ---------------- Haar DWT (outputs tf32-rounded) ----------------------------
__global__ void k_dwt(const float* __restrict__ x) {
    int idx = blockIdx.x * 256 + threadIdx.x;
    if (idx >= NSUB) return;
    int j  = idx & 127;
    int i  = (idx >> 7) & 127;
    int bc = idx >> 14;
    const float* xp = x + ((size_t)bc * 256 + 2 * i) * 256 + 2 * j;
    float2 t0 = *(const float2*)xp;
    float2 t1 = *(const float2*)(xp + 256);
    float a = t0.x, b = t0.y, c = t1.x, d = t1.y;
    g_ll[idx] = tf32r((a + b + c + d) * 0.5f);
    g_lh[idx] = tf32r((a - b + c - d) * 0.5f);
    g_hl[idx] = tf32r((a + b - c - d) * 0.5f);
    g_hh[idx] = tf32r((a - b - c + d) * 0.5f);
}

// ---------------- merged 3x3 convs, tf32 MMA, 512 thr, 32x16 tile ------------
// grid (4,8,40): z: grp = z>>3, b = z&7. Spatial tile 32 cols x 16 rows (N=512).
// grp: 0 lh->h1[0:64], 1 hl->h1[64:128], 2 lh->yh[0:64], 3 hl->yh[64:128],
//      4 hh->yh[128:192]. All relu. 16 warps: 2m x 8n.
__global__ void __launch_bounds__(512, 1) k_conv3x3_mma() {
    extern __shared__ unsigned sm3[];
    int tx = blockIdx.x, ty = blockIdx.y;
    int bz = blockIdx.z;
    int grp = bz >> 3, b = bz & 7;

    const float* in;
    float* out;
    int ostr;
    if (grp == 0)      { in = g_lh; out = g_h1;                      ostr = 128 * PX; }
    else if (grp == 1) { in = g_hl; out = g_h1 + (size_t)64 * PX;    ostr = 128 * PX; }
    else if (grp == 2) { in = g_lh; out = g_yh;                      ostr = 192 * PX; }
    else if (grp == 3) { in = g_hl; out = g_yh + (size_t)64 * PX;    ostr = 192 * PX; }
    else               { in = g_hh; out = g_yh + (size_t)128 * PX;   ostr = 192 * PX; }
    const float* wsc = g_w3 + (size_t)grp * W3_GROUP;

    int tid  = threadIdx.x;
    int wp   = tid >> 5;
    int lane = tid & 31;
    int gid  = lane >> 2, tg = lane & 3;
    int mh = wp & 1;          // m half: tiles {mh*32, mh*32+16}
    int nq = wp >> 1;         // n octant: 64 px
    int gy0  = ty * 16 - 1;
    int gx0s = tx * 32 - 4;
    unsigned smaddr = (unsigned)__cvta_generic_to_shared(sm3);
    const float* ib0 = in + (size_t)b * 64 * PX;

    int posB[8];
#pragma unroll
    for (int nt = 0; nt < 8; nt++) {
        int n = nq * 64 + nt * 8 + gid;
        posB[nt] = (n >> 5) * ROW_STR + (n & 31) + 3;
    }

    float acc[2][8][4];
#pragma unroll
    for (int mt = 0; mt < 2; mt++)
#pragma unroll
        for (int t = 0; t < 8; t++) {
            acc[mt][t][0] = acc[mt][t][1] = acc[mt][t][2] = acc[mt][t][3] = 0.f;
        }

    // image: 8 ci x 18 rows x 10 segments of 4 floats (16B each) = 1440 copies
#define STAGE3(CH) {                                                            \
    int c8 = (CH);                                                              \
    unsigned base3 = smaddr + (unsigned)((c8 & 1) * BUF3) * 4u;                 \
    const float* ib = ib0 + (size_t)c8 * 8 * PX;                                \
    for (int l = tid; l < 1440; l += 512) {                                     \
        int ciL = l / 180, rr = l - ciL * 180;                                  \
        int row = rr / 10, s = rr - row * 10;                                   \
        int gy = gy0 + row;                                                     \
        int gxs = gx0s + s * 4;                                                 \
        bool ok = ((unsigned)gy < 128u) && ((unsigned)gxs <= 124u);             \
        const float* srcp = ib + (size_t)ciL * PX + (ok ? (gy * 128 + gxs) : 0);\
        int sz = ok ? 16 : 0;                                                   \
        CP16Z(base3 + (unsigned)(ciL * CI_STR + row * ROW_STR + s * 4) * 4u,    \
              srcp, sz);                                                        \
    }                                                                           \
    const float4* ws3 = (const float4*)(wsc + (size_t)c8 * WCH3);               \
    unsigned wb3 = base3 + (unsigned)IMG3 * 4u;                                 \
    for (int l = tid; l < 1152; l += 512)                                       \
        CP16(wb3 + (unsigned)l * 16u, ws3 + l);                                 \
    CP_COMMIT(); }

    STAGE3(0);
    int t0 = mh * 32;
    int s0 = (tg + ((t0 + gid) >> 2)) & 3;   // slot for rows o, o+16
    int s8 = (s0 + 2) & 3;                   // slot for rows o+8, o+24

    for (int ch = 0; ch < 8; ch++) {
        CP_WAIT0();
        __syncthreads();
        if (ch < 7) STAGE3(ch + 1);

        const unsigned* bufc = sm3 + (ch & 1) * BUF3;
        const unsigned* w_s  = bufc + IMG3;
#pragma unroll
        for (int d = 0; d < 9; d++) {
            const unsigned* ap = w_s + (d * 64 + t0 + gid) * 8;
            uint2 A0  = *(const uint2*)(ap + 2 * s0);          // rows o     : k tg, tg+4
            uint2 A8  = *(const uint2*)(ap + 64 + 2 * s8);     // rows o+8
            uint2 A16 = *(const uint2*)(ap + 128 + 2 * s0);    // rows o+16
            uint2 A24 = *(const uint2*)(ap + 192 + 2 * s8);    // rows o+24
            int dOff = (d / 3) * ROW_STR + (d % 3);
            const unsigned* bw = bufc + tg * CI_STR + dOff;
#pragma unroll
            for (int nt = 0; nt < 8; nt++) {
                unsigned b0 = bw[posB[nt]];
                unsigned b1 = bw[posB[nt] + 4 * CI_STR];
                MMA_TF32(acc[0][nt][0], acc[0][nt][1], acc[0][nt][2], acc[0][nt][3],
                         A0.x, A8.x, A0.y, A8.y, b0, b1);
                MMA_TF32(acc[1][nt][0], acc[1][nt][1], acc[1][nt][2], acc[1][nt][3],
                         A16.x, A24.x, A16.y, A24.y, b0, b1);
            }
        }
    }
#undef STAGE3

    float* ob = out + (size_t)b * ostr;
#pragma unroll
    for (int mt = 0; mt < 2; mt++) {
        int o = mh * 32 + mt * 16 + gid;
#pragma unroll
        for (int nt = 0; nt < 8; nt++) {
            int n = nq * 64 + nt * 8 + tg * 2;
            int gy = ty * 16 + (n >> 5), gx = tx * 32 + (n & 31);
            float* p0 = ob + (size_t)o * PX + gy * 128 + gx;
            *(float2*)p0 = make_float2(tf32r(fmaxf(acc[mt][nt][0], 0.f)),
                                       tf32r(fmaxf(acc[mt][nt][1], 0.f)));
            float* p1 = p0 + 8 * PX;
            *(float2*)p1 = make_float2(tf32r(fmaxf(acc[mt][nt][2], 0.f)),
                                       tf32r(fmaxf(acc[mt][nt][3], 0.f)));
        }
    }
}

// ---------------- 1x1 conv body, tf32 MMA, 2-stage pipeline ------------------
// mode: 0 = plain, 1 = relu, 2 = fused IDWT epilogue (out = final 256x256, aux = yh)
__device__ __forceinline__ void conv1x1_body(
        const float* __restrict__ in, float* __restrict__ out,
        const float* __restrict__ wsc, int nch, int inBstride, int mode,
        const float* __restrict__ aux, int b, unsigned* sm1) {
    int p0blk = blockIdx.x * 256;
    int tid  = threadIdx.x;
    int wp   = tid >> 5;
    int lane = tid & 31;
    int gid  = lane >> 2, tg = lane & 3;
    int mh = wp & 1;
    int nq = wp >> 1;
    unsigned smaddr = (unsigned)__cvta_generic_to_shared(sm1);
    const float* ib = in + (size_t)b * inBstride + p0blk;

    float acc[2][8][4];
#pragma unroll
    for (int mt = 0; mt < 2; mt++)
#pragma unroll
        for (int t = 0; t < 8; t++) {
            acc[mt][t][0] = acc[mt][t][1] = acc[mt][t][2] = acc[mt][t][3] = 0.f;
        }

#define STAGE1(CH) {                                                            \
    int c8 = (CH);                                                              \
    unsigned base1 = smaddr + (unsigned)((c8 & 1) * BUF1) * 4u;                 \
    for (int l = tid; l < 1024; l += 256) {                                     \
        int ciL = l >> 6, p4 = l & 63;                                          \
        const float4* srcp = (const float4*)(ib + (size_t)(c8 * 16 + ciL) * PX) + p4; \
        CP16(base1 + (unsigned)(ciL * IN1_STR + p4 * 4) * 4u, srcp);            \
    }                                                                           \
    const float4* ws1 = (const float4*)(wsc + (size_t)c8 * 1152);               \
    unsigned wb1 = base1 + 4224u * 4u;                                          \
    for (int l = tid; l < 288; l += 256)                                        \
        CP16(wb1 + (unsigned)l * 16u, ws1 + l);                                 \
    CP_COMMIT(); }

    STAGE1(0);
    for (int ch = 0; ch < nch; ch++) {
        CP_WAIT0();
        __syncthreads();
        if (ch + 1 < nch) STAGE1(ch + 1);

        const unsigned* bufc = sm1 + (ch & 1) * BUF1;
        const unsigned* w_s  = bufc + 4224;
#pragma unroll
        for (int ks = 0; ks < 2; ks++) {
            const unsigned* aw  = w_s + (ks * 8 + tg) * W_STR + mh * 32 + gid;
            const unsigned* aw4 = aw + 4 * W_STR;
            unsigned a0  = aw[0],  a1  = aw[8],  a2  = aw4[0],  a3  = aw4[8];
            unsigned a0b = aw[16], a1b = aw[24], a2b = aw4[16], a3b = aw4[24];
            const unsigned* bw = bufc + (ks * 8 + tg) * IN1_STR + nq * 64;
#pragma unroll
            for (int nt = 0; nt < 8; nt++) {
                unsigned b0 = bw[nt * 8 + gid];
                unsigned b1 = bw[4 * IN1_STR + nt * 8 + gid];
                MMA_TF32(acc[0][nt][0], acc[0][nt][1], acc[0][nt][2], acc[0][nt][3],
                         a0, a1, a2, a3, b0, b1);
                MMA_TF32(acc[1][nt][0], acc[1][nt][1], acc[1][nt][2], acc[1][nt][3],
                         a0b, a1b, a2b, a3b, b0, b1);
            }
        }
    }
#undef STAGE1

    if (mode != 2) {
        float* ob = out + (size_t)b * 64 * PX + p0blk;
#pragma unroll
        for (int mt = 0; mt < 2; mt++) {
            int o = mh * 32 + mt * 16 + gid;
#pragma unroll
            for (int nt = 0; nt < 8; nt++) {
                int n = nq * 64 + nt * 8 + tg * 2;
                float2 r0 = make_float2(acc[mt][nt][0], acc[mt][nt][1]);
                float2 r1 = make_float2(acc[mt][nt][2], acc[mt][nt][3]);
                if (mode == 1) {
                    r0.x = fmaxf(r0.x, 0.f); r0.y = fmaxf(r0.y, 0.f);
                    r1.x = fmaxf(r1.x, 0.f); r1.y = fmaxf(r1.y, 0.f);
                }
                *(float2*)(ob + (size_t)o * PX + n)       = r0;
                *(float2*)(ob + (size_t)(o + 8) * PX + n) = r1;
            }
        }
    } else {
        // fused IDWT: ll = acc (proj output), lh/hl/hh from aux (= g_yh)
        const float* yb = aux + (size_t)b * 192 * PX;
        float* ob2 = out + (size_t)b * 64 * 65536;
#pragma unroll
        for (int mt = 0; mt < 2; mt++) {
#pragma unroll
            for (int nt = 0; nt < 8; nt++) {
                int n = nq * 64 + nt * 8 + tg * 2;
                int p = p0blk + n;
                int i = p >> 7, j = p & 127;
#pragma unroll
                for (int half = 0; half < 2; half++) {
                    int c = mh * 32 + mt * 16 + gid + half * 8;
                    float ll0 = acc[mt][nt][half * 2];
                    float ll1 = acc[mt][nt][half * 2 + 1];
                    const float* yc = yb + (size_t)c * PX + p;
                    float2 lh = *(const float2*)yc;
                    float2 hl = *(const float2*)(yc + (size_t)64 * PX);
                    float2 hh = *(const float2*)(yc + (size_t)128 * PX);
                    float4 top, bot;
                    top.x = (ll0 + lh.x + hl.x + hh.x) * 0.5f;
                    top.y = (ll0 - lh.x + hl.x - hh.x) * 0.5f;
                    bot.x = (ll0 + lh.x - hl.x - hh.x) * 0.5f;
                    bot.y = (ll0 - lh.x - hl.x + hh.x) * 0.5f;
                    top.z = (ll1 + lh.y + hl.y + hh.y) * 0.5f;
                    top.w = (ll1 - lh.y + hl.y - hh.y) * 0.5f;
                    bot.z = (ll1 + lh.y - hl.y - hh.y) * 0.5f;
                    bot.w = (ll1 - lh.y - hl.y + hh.y) * 0.5f;
                    float* op = ob2 + ((size_t)c * 256 + 2 * i) * 256 + 2 * j;
                    *(float4*)op         = top;
                    *(float4*)(op + 256) = bot;
                }
            }
        }
    }
}

// merged qkv + high2 launch: grid (64, 16); y<8 -> qkv(b=y), else high2(b=y-8)
__global__ void __launch_bounds__(256, 2) k_conv1x1_pair() {
    extern __shared__ unsigned smp[];
    int y = blockIdx.y;
    if (y < 8) {
        conv1x1_body(g_ll, g_t, g_w1 + W1_QKV_OFF, 4, 64 * PX, 0, nullptr, y, smp);
    } else {
        conv1x1_body(g_h1, g_filt, g_w1 + W1_H2_OFF, 8, 128 * PX, 1, nullptr, y - 8, smp);
    }
}

// proj (+ fused IDWT): grid (64, 8)
__global__ void __launch_bounds__(256, 2) k_conv1x1_proj(float* __restrict__ out) {
    extern __shared__ unsigned smp[];
    conv1x1_body(g_z, out, g_w1 + W1_PROJ_OFF, 4, 64 * PX, 2, g_yh, blockIdx.y, smp);
}

// ---------------- window attention + fused depthwise 3x3 ---------------------
// dynamic smem: qs[4096] vsm[4096] tp[6400] scl[256] tbl[900] stemp[4] sdw[576]
#define ATTN_SMEM_WORDS 16328
__global__ void __launch_bounds__(256) k_attn(
        const float* __restrict__ table, const float* __restrict__ temp,
        const float* __restrict__ wdw) {
    extern __shared__ float sA[];
    float* qs    = sA;
    float* vsm   = sA + 4096;
    float* tp    = sA + 8192;
    float* scl   = sA + 14592;
    float* tbl   = sA + 14848;
    float* stemp = sA + 15748;
    float* sdw   = sA + 15752;

    int bw = blockIdx.x;
    int b  = bw >> 8;
    int wr = (bw >> 4) & 15;
    int wc = bw & 15;
    int tid = threadIdx.x;

    if (tid < 4) stemp[tid] = temp[tid];
    for (int l = tid; l < 900; l += 256) tbl[l] = table[l];
    for (int l = tid; l < 576; l += 256) sdw[l] = wdw[l];

    // t-patch (10x10 per channel) for depthwise
    for (int l = tid; l < 6400; l += 256) {
        int c = l / 100, p = l - c * 100;
        int py = p / 10, px = p - py * 10;
        int gy = wr * 8 - 1 + py, gx = wc * 8 - 1 + px;
        float v = 0.f;
        if ((unsigned)gy < 128u && (unsigned)gx < 128u)
            v = g_t[((size_t)b * 64 + c) * PX + gy * 128 + gx];
        tp[l] = v;
    }
    // q (shifted ll)
    for (int l = tid; l < 4096; l += 256) {
        int c = l >> 6, n = l & 63;
        int y = n >> 3, x = n & 7;
        int qy = (wr * 8 + y + 4) & 127;
        int qx = (wc * 8 + x + 4) & 127;
        qs[l] = g_ll[((size_t)b * 64 + c) * PX + qy * 128 + qx];
    }
    __syncthreads();

    // depthwise + filt -> vsm
    for (int l = tid; l < 4096; l += 256) {
        int c = l >> 6, n = l & 63;
        int y = n >> 3, x = n & 7;
        const float* tc = tp + c * 100;
        const float* wc9 = sdw + c * 9;
        float a0 = 0.f;
#pragma unroll
        for (int dy = 0; dy < 3; dy++)
#pragma unroll
            for (int dx = 0; dx < 3; dx++)
                a0 = fmaf(wc9[dy * 3 + dx], tc[(y + dy) * 10 + x + dx], a0);
        float ft = g_filt[((size_t)b * 64 + c) * PX + (wr * 8 + y) * 128 + wc * 8 + x];
        vsm[l] = a0 * (1.0f + ft);
    }
    __syncthreads();

    {
        int h = tid >> 6, n = tid & 63;
        float s = 0.f;
#pragma unroll
        for (int d = 0; d < 16; d++) { float v = qs[(h * 16 + d) * 64 + n]; s += v * v; }
        scl[tid] = 1.0f / fmaxf(sqrtf(s), 1e-12f);
    }
    __syncthreads();

    int h = tid >> 6, n = tid & 63;
    int yn = n >> 3, xn = n & 7;
    float myscl = scl[tid];
    float tph = stemp[h];

    float qn[16];
#pragma unroll
    for (int d = 0; d < 16; d++) qn[d] = qs[(h * 16 + d) * 64 + n] * myscl;

    float a[64];
    for (int m = 0; m < 64; m++) {
        float s = 0.f;
#pragma unroll
        for (int d = 0; d < 16; d++) s = fmaf(qn[d], qs[(h * 16 + d) * 64 + m], s);
        s *= scl[(h << 6) | m];
        int ym = m >> 3, xm = m & 7;
        int ridx = (yn - ym + 7) * 15 + (xn - xm + 7);
        a[m] = (s + tbl[ridx * 4 + h]) * tph;
    }

    float mx = -1e30f;
#pragma unroll
    for (int m = 0; m < 64; m++) mx = fmaxf(mx, a[m]);
    float sum = 0.f;
#pragma unroll
    for (int m = 0; m < 64; m++) { float e = expf(a[m] - mx); a[m] = e; sum += e; }
    float inv = 1.0f / sum;

    float o[16];
#pragma unroll
    for (int d = 0; d < 16; d++) o[d] = 0.f;
    for (int m = 0; m < 64; m++) {
        float am = a[m] * inv;
#pragma unroll
        for (int d = 0; d < 16; d++) o[d] = fmaf(vsm[(h * 16 + d) * 64 + m], am, o[d]);
    }

    int oy = (wr * 8 + yn + 4) & 127;
    int ox = (wc * 8 + xn + 4) & 127;
#pragma unroll
    for (int d = 0; d < 16; d++)
        g_z[((size_t)b * 64 + h * 16 + d) * PX + oy * 128 + ox] = tf32r(o[d]);
}

// ---------------- launcher ---------------------------------------------------
extern "C" void kernel_launch(void* const* d_in, const int* in_sizes, int n_in,
                              void* d_out, int out_size) {
    const float* x           = (const float*)d_in[0];
    const float* temperature = (const float*)d_in[1];
    const float* rel_bias    = (const float*)d_in[2];
    const float* w_high1     = (const float*)d_in[3];
    const float* w_high2     = (const float*)d_in[4];
    const float* w_highout   = (const float*)d_in[5];
    const float* w_qkv       = (const float*)d_in[6];
    const float* w_dwconv    = (const float*)d_in[7];
    const float* w_proj      = (const float*)d_in[8];
    float* out = (float*)d_out;

    static int smem_set = 0;
    if (!smem_set) {
        cudaFuncSetAttribute(k_conv3x3_mma,
            cudaFuncAttributeMaxDynamicSharedMemorySize, 2 * BUF3 * 4);
        cudaFuncSetAttribute(k_conv1x1_pair,
            cudaFuncAttributeMaxDynamicSharedMemorySize, 2 * BUF1 * 4);
        cudaFuncSetAttribute(k_conv1x1_proj,
            cudaFuncAttributeMaxDynamicSharedMemorySize, 2 * BUF1 * 4);
        cudaFuncSetAttribute(k_attn,
            cudaFuncAttributeMaxDynamicSharedMemorySize, ATTN_SMEM_WORDS * 4);
        smem_set = 1;
    }

    int nb = (NSUB + 255) / 256;
    dim3 g3(4, 8, 40);
    dim3 gpair(PX / 256, 16);
    dim3 gproj(PX / 256, 8);
    int dyn3 = 2 * BUF3 * 4;
    int dyn1 = 2 * BUF1 * 4;
    int dynA = ATTN_SMEM_WORDS * 4;

    // 1. weight prep
    k_prepw<<<(5 * W3_GROUP + 18432 + 255) / 256, 256>>>(w_high1, w_highout, w_high2, w_qkv, w_proj);
    // 2. DWT
    k_dwt<<<nb, 256>>>(x);
    // 3. all five grouped 3x3 convs (high1 x2 + highout x3), relu, merged
    k_conv3x3_mma<<<g3, 512, dyn3>>>();
    // 4. qkv (-> t) and high2 (-> filt) 1x1 convs, merged launch
    k_conv1x1_pair<<<gpair, 256, dyn1>>>();
    // 5. attention with fused depthwise (roll fused) -> z
    k_attn<<<2048, 256, dynA>>>(rel_bias, temperature, w_dwconv + 128 * 9);
    // 6. proj 1x1 with fused IDWT -> out
    k_conv1x1_proj<<<gproj, 256, dyn1>>>(out);
}

// round 15
// speedup vs baseline: 1.0387x; 1.0387x over previous
#include <cuda_runtime.h>
#include <cstdint>
#include <math.h>

#define BB 8
#define CC 64
#define H2 128
#define W2 128
#define PX (H2*W2)          // 16384
#define NSUB (BB*CC*PX)     // 8388608

// conv3x3 smem image: [ci][18 rows][24 cols], col c <-> gx = tx*16-4+c
#define ROW_STR 24
#define CI_STR 440          // 432 padded to 440 (mod 32 = 24 -> tg banks {0,24,16,8})
#define IMG3 3520           // 8 * CI_STR
#define WCH3 4608           // weights per chunk: 9*64*8
#define BUF3 (IMG3 + WCH3)  // 8128 words per buffer

#define IN1_STR 264
#define W_STR 72
#define BUF1 5376

#define W3_GROUP 36864      // 8 chunks * 4608
#define W1_H2_OFF 0
#define W1_QKV_OFF 9216
#define W1_PROJ_OFF 13824

// ---------------- scratch (device globals; no runtime allocation) -----------
__device__ float g_ll[NSUB];
__device__ float g_lh[NSUB];
__device__ float g_hl[NSUB];
__device__ float g_hh[NSUB];
__device__ float g_h1[2*NSUB];
__device__ float g_filt[NSUB];
__device__ float g_t[NSUB];
__device__ float g_z[NSUB];
__device__ float g_yh[3*NSUB];
__device__ float g_w3[5*W3_GROUP];
__device__ float g_w1[18432];

// ---------------- helpers ----------------------------------------------------
__device__ __forceinline__ unsigned f2tf(float f) {
    unsigned u;
    asm("cvt.rna.tf32.f32 %0, %1;" : "=r"(u) : "f"(f));
    return u;
}
__device__ __forceinline__ float tf32r(float f) { return __uint_as_float(f2tf(f)); }

#define MMA_TF32(c0,c1,c2,c3,a0,a1,a2,a3,b0,b1)                                \
    asm volatile("mma.sync.aligned.m16n8k8.row.col.f32.tf32.tf32.f32 "          \
        "{%0,%1,%2,%3}, {%4,%5,%6,%7}, {%8,%9}, {%0,%1,%2,%3};\n"               \
        : "+f"(c0), "+f"(c1), "+f"(c2), "+f"(c3)                                \
        : "r"(a0), "r"(a1), "r"(a2), "r"(a3), "r"(b0), "r"(b1))

#define CP16(dst, src) \
    asm volatile("cp.async.ca.shared.global [%0], [%1], 16;\n" :: "r"(dst), "l"(src))
#define CP16Z(dst, src, sz) \
    asm volatile("cp.async.ca.shared.global [%0], [%1], 16, %2;\n" :: "r"(dst), "l"(src), "r"(sz))
#define CP_COMMIT()  asm volatile("cp.async.commit_group;\n")
#define CP_WAIT0()   asm volatile("cp.async.wait_group 0;\n" ::: "memory")

// ---------------- merged DWT + weight prep -----------------------------------
// blocks [0, nbDwt): Haar DWT (tf32-rounded). blocks [nbDwt, ...): weight prep.
__global__ void k_dwt_prepw(const float* __restrict__ x, int nbDwt,
                            const float* __restrict__ w_high1,
                            const float* __restrict__ w_highout,
                            const float* __restrict__ w_high2,
                            const float* __restrict__ w_qkv,
                            const float* __restrict__ w_proj) {
    if (blockIdx.x < (unsigned)nbDwt) {
        int idx = blockIdx.x * 256 + threadIdx.x;
        int j  = idx & 127;
        int i  = (idx >> 7) & 127;
        int bc = idx >> 14;
        const float* xp = x + ((size_t)bc * 256 + 2 * i) * 256 + 2 * j;
        float2 t0 = *(const float2*)xp;
        float2 t1 = *(const float2*)(xp + 256);
        float a = t0.x, b = t0.y, c = t1.x, d = t1.y;
        g_ll[idx] = tf32r((a + b + c + d) * 0.5f);
        g_lh[idx] = tf32r((a - b + c - d) * 0.5f);
        g_hl[idx] = tf32r((a + b - c - d) * 0.5f);
        g_hh[idx] = tf32r((a - b - c + d) * 0.5f);
        return;
    }
    int idx = (blockIdx.x - nbDwt) * 256 + threadIdx.x;
    const int total3 = 5 * W3_GROUP;   // 184320
    if (idx < total3) {
        // layout per group/chunk: word = (d*64 + o)*8 + 2*slot + par
        //   slot = ((ci&3) + (o>>2)) & 3, par = ci>>2
        int g = idx / W3_GROUP, r = idx - g * W3_GROUP;
        int ch = r / WCH3;  int w = r - ch * WCH3;
        int d = w / 512;    int rem = w - d * 512;
        int o = rem >> 3;   int s = rem & 7;
        int slot = s >> 1, par = s & 1;
        int ci = par * 4 + ((slot - (o >> 2)) & 3);
        const float* src = (g < 2) ? (w_high1 + g * 36864)
                                   : (w_highout + (g - 2) * 36864);
        float v = src[((size_t)o * 64 + ch * 8 + ci) * 9 + d];
        g_w3[idx] = tf32r(v);
    }
    int i1 = idx - total3;
    if (i1 >= 0 && i1 < 18432) {
        float v = 0.f;
        if (i1 < 9216) {               // high2: KC=128
            int ch = i1 / 1152, r = i1 - ch * 1152;
            int ci = r / 72, o = r - ci * 72;
            if (o < 64) v = w_high2[(size_t)o * 128 + ch * 16 + ci];
        } else if (i1 < 13824) {       // qkv v-slice: KC=64
            int r2 = i1 - 9216;
            int ch = r2 / 1152, r = r2 - ch * 1152;
            int ci = r / 72, o = r - ci * 72;
            if (o < 64) v = w_qkv[128 * 64 + (size_t)o * 64 + ch * 16 + ci];
        } else {                       // proj: KC=64
            int r2 = i1 - 13824;
            int ch = r2 / 1152, r = r2 - ch * 1152;
            int ci = r / 72, o = r - ci * 72;
            if (o < 64) v = w_proj[(size_t)o * 64 + ch * 16 + ci];
        }
        g_w1[i1] = tf32r(v);
    }
}

// ---------------- merged 3x3 convs, tf32 MMA, 2m x 4n warp tiling ------------
// grid (8,8,40): z: grp = z>>3, b = z&7.
// grp: 0 lh->h1[0:64], 1 hl->h1[64:128], 2 lh->yh[0:64], 3 hl->yh[64:128],
//      4 hh->yh[128:192]. All relu.
__global__ void __launch_bounds__(256, 2) k_conv3x3_mma() {
    extern __shared__ unsigned sm3[];
    int tx = blockIdx.x, ty = blockIdx.y;
    int bz = blockIdx.z;
    int grp = bz >> 3, b = bz & 7;

    const float* in;
    float* out;
    int ostr;
    if (grp == 0)      { in = g_lh; out = g_h1;                      ostr = 128 * PX; }
    else if (grp == 1) { in = g_hl; out = g_h1 + (size_t)64 * PX;    ostr = 128 * PX; }
    else if (grp == 2) { in = g_lh; out = g_yh;                      ostr = 192 * PX; }
    else if (grp == 3) { in = g_hl; out = g_yh + (size_t)64 * PX;    ostr = 192 * PX; }
    else               { in = g_hh; out = g_yh + (size_t)128 * PX;   ostr = 192 * PX; }
    const float* wsc = g_w3 + (size_t)grp * W3_GROUP;

    int tid  = threadIdx.x;
    int wp   = tid >> 5;
    int lane = tid & 31;
    int gid  = lane >> 2, tg = lane & 3;
    int mh = wp & 1;          // m half: tiles {mh*32, mh*32+16}
    int nq = wp >> 1;         // n quarter: 64 px
    int gy0  = ty * 16 - 1;
    int gx0s = tx * 16 - 4;
    unsigned smaddr = (unsigned)__cvta_generic_to_shared(sm3);
    const float* ib0 = in + (size_t)b * 64 * PX;

    int posB[8];
#pragma unroll
    for (int nt = 0; nt < 8; nt++) {
        int n = nq * 64 + nt * 8 + gid;
        posB[nt] = (n >> 4) * ROW_STR + (n & 15) + 3;
    }

    float acc[2][8][4];
#pragma unroll
    for (int mt = 0; mt < 2; mt++)
#pragma unroll
        for (int t = 0; t < 8; t++) {
            acc[mt][t][0] = acc[mt][t][1] = acc[mt][t][2] = acc[mt][t][3] = 0.f;
        }

    // image: 8 ci x 18 rows x 6 segments of 4 floats (16B each) = 864 copies
#define STAGE3(CH) {                                                            \
    int c8 = (CH);                                                              \
    unsigned base3 = smaddr + (unsigned)((c8 & 1) * BUF3) * 4u;                 \
    const float* ib = ib0 + (size_t)c8 * 8 * PX;                                \
    for (int l = tid; l < 864; l += 256) {                                      \
        int ciL = l / 108, rr = l - ciL * 108;                                  \
        int row = rr / 6, s = rr - row * 6;                                     \
        int gy = gy0 + row;                                                     \
        int gxs = gx0s + s * 4;                                                 \
        bool ok = ((unsigned)gy < 128u) && ((unsigned)gxs <= 124u);             \
        const float* srcp = ib + (size_t)ciL * PX + (ok ? (gy * 128 + gxs) : 0);\
        int sz = ok ? 16 : 0;                                                   \
        CP16Z(base3 + (unsigned)(ciL * CI_STR + row * ROW_STR + s * 4) * 4u,    \
              srcp, sz);                                                        \
    }                                                                           \
    const float4* ws3 = (const float4*)(wsc + (size_t)c8 * WCH3);               \
    unsigned wb3 = base3 + (unsigned)IMG3 * 4u;                                 \
    for (int l = tid; l < 1152; l += 256)                                       \
        CP16(wb3 + (unsigned)l * 16u, ws3 + l);                                 \
    CP_COMMIT(); }

    STAGE3(0);
    int t0 = mh * 32;
    int s0 = (tg + ((t0 + gid) >> 2)) & 3;   // slot for rows o, o+16
    int s8 = (s0 + 2) & 3;                   // slot for rows o+8, o+24

    for (int ch = 0; ch < 8; ch++) {
        CP_WAIT0();
        __syncthreads();
        if (ch < 7) STAGE3(ch + 1);

        const unsigned* bufc = sm3 + (ch & 1) * BUF3;
        const unsigned* w_s  = bufc + IMG3;
#pragma unroll
        for (int d = 0; d < 9; d++) {
            const unsigned* ap = w_s + (d * 64 + t0 + gid) * 8;
            uint2 A0  = *(const uint2*)(ap + 2 * s0);          // rows o     : k tg, tg+4
            uint2 A8  = *(const uint2*)(ap + 64 + 2 * s8);     // rows o+8
            uint2 A16 = *(const uint2*)(ap + 128 + 2 * s0);    // rows o+16
            uint2 A24 = *(const uint2*)(ap + 192 + 2 * s8);    // rows o+24
            int dOff = (d / 3) * ROW_STR + (d % 3);
            const unsigned* bw = bufc + tg * CI_STR + dOff;
#pragma unroll
            for (int nt = 0; nt < 8; nt++) {
                unsigned b0 = bw[posB[nt]];
                unsigned b1 = bw[posB[nt] + 4 * CI_STR];
                MMA_TF32(acc[0][nt][0], acc[0][nt][1], acc[0][nt][2], acc[0][nt][3],
                         A0.x, A8.x, A0.y, A8.y, b0, b1);
                MMA_TF32(acc[1][nt][0], acc[1][nt][1], acc[1][nt][2], acc[1][nt][3],
                         A16.x, A24.x, A16.y, A24.y, b0, b1);
            }
        }
    }
#undef STAGE3

    float* ob = out + (size_t)b * ostr;
#pragma unroll
    for (int mt = 0; mt < 2; mt++) {
        int o = mh * 32 + mt * 16 + gid;
#pragma unroll
        for (int nt = 0; nt < 8; nt++) {
            int n = nq * 64 + nt * 8 + tg * 2;
            int gy = ty * 16 + (n >> 4), gx = tx * 16 + (n & 15);
            float* p0 = ob + (size_t)o * PX + gy * 128 + gx;
            *(float2*)p0 = make_float2(tf32r(fmaxf(acc[mt][nt][0], 0.f)),
                                       tf32r(fmaxf(acc[mt][nt][1], 0.f)));
            float* p1 = p0 + 8 * PX;
            *(float2*)p1 = make_float2(tf32r(fmaxf(acc[mt][nt][2], 0.f)),
                                       tf32r(fmaxf(acc[mt][nt][3], 0.f)));
        }
    }
}

// ---------------- 1x1 conv body, tf32 MMA, 2-stage pipeline ------------------
// mode: 0 = plain, 1 = relu, 2 = fused IDWT epilogue (out = final 256x256, aux = yh)
__device__ __forceinline__ void conv1x1_body(
        const float* __restrict__ in, float* __restrict__ out,
        const float* __restrict__ wsc, int nch, int inBstride, int mode,
        const float* __restrict__ aux, int b, unsigned* sm1) {
    int p0blk = blockIdx.x * 256;
    int tid  = threadIdx.x;
    int wp   = tid >> 5;
    int lane = tid & 31;
    int gid  = lane >> 2, tg = lane & 3;
    int mh = wp & 1;
    int nq = wp >> 1;
    unsigned smaddr = (unsigned)__cvta_generic_to_shared(sm1);
    const float* ib = in + (size_t)b * inBstride + p0blk;

    float acc[2][8][4];
#pragma unroll
    for (int mt = 0; mt < 2; mt++)
#pragma unroll
        for (int t = 0; t < 8; t++) {
            acc[mt][t][0] = acc[mt][t][1] = acc[mt][t][2] = acc[mt][t][3] = 0.f;
        }

#define STAGE1(CH) {                                                            \
    int c8 = (CH);                                                              \
    unsigned base1 = smaddr + (unsigned)((c8 & 1) * BUF1) * 4u;                 \
    for (int l = tid; l < 1024; l += 256) {                                     \
        int ciL = l >> 6, p4 = l & 63;                                          \
        const float4* srcp = (const float4*)(ib + (size_t)(c8 * 16 + ciL) * PX) + p4; \
        CP16(base1 + (unsigned)(ciL * IN1_STR + p4 * 4) * 4u, srcp);            \
    }                                                                           \
    const float4* ws1 = (const float4*)(wsc + (size_t)c8 * 1152);               \
    unsigned wb1 = base1 + 4224u * 4u;                                          \
    for (int l = tid; l < 288; l += 256)                                        \
        CP16(wb1 + (unsigned)l * 16u, ws1 + l);                                 \
    CP_COMMIT(); }

    STAGE1(0);
    for (int ch = 0; ch < nch; ch++) {
        CP_WAIT0();
        __syncthreads();
        if (ch + 1 < nch) STAGE1(ch + 1);

        const unsigned* bufc = sm1 + (ch & 1) * BUF1;
        const unsigned* w_s  = bufc + 4224;
#pragma unroll
        for (int ks = 0; ks < 2; ks++) {
            const unsigned* aw  = w_s + (ks * 8 + tg) * W_STR + mh * 32 + gid;
            const unsigned* aw4 = aw + 4 * W_STR;
            unsigned a0  = aw[0],  a1  = aw[8],  a2  = aw4[0],  a3  = aw4[8];
            unsigned a0b = aw[16], a1b = aw[24], a2b = aw4[16], a3b = aw4[24];
            const unsigned* bw = bufc + (ks * 8 + tg) * IN1_STR + nq * 64;
#pragma unroll
            for (int nt = 0; nt < 8; nt++) {
                unsigned b0 = bw[nt * 8 + gid];
                unsigned b1 = bw[4 * IN1_STR + nt * 8 + gid];
                MMA_TF32(acc[0][nt][0], acc[0][nt][1], acc[0][nt][2], acc[0][nt][3],
                         a0, a1, a2, a3, b0, b1);
                MMA_TF32(acc[1][nt][0], acc[1][nt][1], acc[1][nt][2], acc[1][nt][3],
                         a0b, a1b, a2b, a3b, b0, b1);
            }
        }
    }
#undef STAGE1

    if (mode != 2) {
        float* ob = out + (size_t)b * 64 * PX + p0blk;
#pragma unroll
        for (int mt = 0; mt < 2; mt++) {
            int o = mh * 32 + mt * 16 + gid;
#pragma unroll
            for (int nt = 0; nt < 8; nt++) {
                int n = nq * 64 + nt * 8 + tg * 2;
                float2 r0 = make_float2(acc[mt][nt][0], acc[mt][nt][1]);
                float2 r1 = make_float2(acc[mt][nt][2], acc[mt][nt][3]);
                if (mode == 1) {
                    r0.x = fmaxf(r0.x, 0.f); r0.y = fmaxf(r0.y, 0.f);
                    r1.x = fmaxf(r1.x, 0.f); r1.y = fmaxf(r1.y, 0.f);
                }
                *(float2*)(ob + (size_t)o * PX + n)       = r0;
                *(float2*)(ob + (size_t)(o + 8) * PX + n) = r1;
            }
        }
    } else {
        // fused IDWT: ll = acc (proj output), lh/hl/hh from aux (= g_yh)
        const float* yb = aux + (size_t)b * 192 * PX;
        float* ob2 = out + (size_t)b * 64 * 65536;
#pragma unroll
        for (int mt = 0; mt < 2; mt++) {
#pragma unroll
            for (int nt = 0; nt < 8; nt++) {
                int n = nq * 64 + nt * 8 + tg * 2;
                int p = p0blk + n;
                int i = p >> 7, j = p & 127;
#pragma unroll
                for (int half = 0; half < 2; half++) {
                    int c = mh * 32 + mt * 16 + gid + half * 8;
                    float ll0 = acc[mt][nt][half * 2];
                    float ll1 = acc[mt][nt][half * 2 + 1];
                    const float* yc = yb + (size_t)c * PX + p;
                    float2 lh = *(const float2*)yc;
                    float2 hl = *(const float2*)(yc + (size_t)64 * PX);
                    float2 hh = *(const float2*)(yc + (size_t)128 * PX);
                    float4 top, bot;
                    top.x = (ll0 + lh.x + hl.x + hh.x) * 0.5f;
                    top.y = (ll0 - lh.x + hl.x - hh.x) * 0.5f;
                    bot.x = (ll0 + lh.x - hl.x - hh.x) * 0.5f;
                    bot.y = (ll0 - lh.x - hl.x + hh.x) * 0.5f;
                    top.z = (ll1 + lh.y + hl.y + hh.y) * 0.5f;
                    top.w = (ll1 - lh.y + hl.y - hh.y) * 0.5f;
                    bot.z = (ll1 + lh.y - hl.y - hh.y) * 0.5f;
                    bot.w = (ll1 - lh.y - hl.y + hh.y) * 0.5f;
                    float* op = ob2 + ((size_t)c * 256 + 2 * i) * 256 + 2 * j;
                    *(float4*)op         = top;
                    *(float4*)(op + 256) = bot;
                }
            }
        }
    }
}

// merged qkv + high2 launch: grid (64, 16); y<8 -> qkv(b=y), else high2(b=y-8)
__global__ void __launch_bounds__(256, 2) k_conv1x1_pair() {
    extern __shared__ unsigned smp[];
    int y = blockIdx.y;
    if (y < 8) {
        conv1x1_body(g_ll, g_t, g_w1 + W1_QKV_OFF, 4, 64 * PX, 0, nullptr, y, smp);
    } else {
        conv1x1_body(g_h1, g_filt, g_w1 + W1_H2_OFF, 8, 128 * PX, 1, nullptr, y - 8, smp);
    }
}

// proj (+ fused IDWT): grid (64, 8)
__global__ void __launch_bounds__(256, 2) k_conv1x1_proj(float* __restrict__ out) {
    extern __shared__ unsigned smp[];
    conv1x1_body(g_z, out, g_w1 + W1_PROJ_OFF, 4, 64 * PX, 2, g_yh, blockIdx.y, smp);
}

// ---------------- window attention + fused depthwise 3x3 ---------------------
// dynamic smem: qs[4096] vsm[4096] tp[6400] scl[256] tbl[900] stemp[4] sdw[576]
#define ATTN_SMEM_WORDS 16328
__global__ void __launch_bounds__(256) k_attn(
        const float* __restrict__ table, const float* __restrict__ temp,
        const float* __restrict__ wdw) {
    extern __shared__ float sA[];
    float* qs    = sA;
    float* vsm   = sA + 4096;
    float* tp    = sA + 8192;
    float* scl   = sA + 14592;
    float* tbl   = sA + 14848;
    float* stemp = sA + 15748;
    float* sdw   = sA + 15752;

    int bw = blockIdx.x;
    int b  = bw >> 8;
    int wr = (bw >> 4) & 15;
    int wc = bw & 15;
    int tid = threadIdx.x;

    if (tid < 4) stemp[tid] = temp[tid];
    for (int l = tid; l < 900; l += 256) tbl[l] = table[l];
    for (int l = tid; l < 576; l += 256) sdw[l] = wdw[l];

    // t-patch (10x10 per channel) for depthwise
    for (int l = tid; l < 6400; l += 256) {
        int c = l / 100, p = l - c * 100;
        int py = p / 10, px = p - py * 10;
        int gy = wr * 8 - 1 + py, gx = wc * 8 - 1 + px;
        float v = 0.f;
        if ((unsigned)gy < 128u && (unsigned)gx < 128u)
            v = g_t[((size_t)b * 64 + c) * PX + gy * 128 + gx];
        tp[l] = v;
    }
    // q (shifted ll)
    for (int l = tid; l < 4096; l += 256) {
        int c = l >> 6, n = l & 63;
        int y = n >> 3, x = n & 7;
        int qy = (wr * 8 + y + 4) & 127;
        int qx = (wc * 8 + x + 4) & 127;
        qs[l] = g_ll[((size_t)b * 64 + c) * PX + qy * 128 + qx];
    }
    __syncthreads();

    // depthwise + filt -> vsm
    for (int l = tid; l < 4096; l += 256) {
        int c = l >> 6, n = l & 63;
        int y = n >> 3, x = n & 7;
        const float* tc = tp + c * 100;
        const float* wc9 = sdw + c * 9;
        float a0 = 0.f;
#pragma unroll
        for (int dy = 0; dy < 3; dy++)
#pragma unroll
            for (int dx = 0; dx < 3; dx++)
                a0 = fmaf(wc9[dy * 3 + dx], tc[(y + dy) * 10 + x + dx], a0);
        float ft = g_filt[((size_t)b * 64 + c) * PX + (wr * 8 + y) * 128 + wc * 8 + x];
        vsm[l] = a0 * (1.0f + ft);
    }
    __syncthreads();

    {
        int h = tid >> 6, n = tid & 63;
        float s = 0.f;
#pragma unroll
        for (int d = 0; d < 16; d++) { float v = qs[(h * 16 + d) * 64 + n]; s += v * v; }
        scl[tid] = 1.0f / fmaxf(sqrtf(s), 1e-12f);
    }
    __syncthreads();

    int h = tid >> 6, n = tid & 63;
    int yn = n >> 3, xn = n & 7;
    float myscl = scl[tid];
    float tph = stemp[h];

    float qn[16];
#pragma unroll
    for (int d = 0; d < 16; d++) qn[d] = qs[(h * 16 + d) * 64 + n] * myscl;

    float a[64];
    for (int m = 0; m < 64; m++) {
        float s = 0.f;
#pragma unroll
        for (int d = 0; d < 16; d++) s = fmaf(qn[d], qs[(h * 16 + d) * 64 + m], s);
        s *= scl[(h << 6) | m];
        int ym = m >> 3, xm = m & 7;
        int ridx = (yn - ym + 7) * 15 + (xn - xm + 7);
        a[m] = (s + tbl[ridx * 4 + h]) * tph;
    }

    float mx = -1e30f;
#pragma unroll
    for (int m = 0; m < 64; m++) mx = fmaxf(mx, a[m]);
    float sum = 0.f;
#pragma unroll
    for (int m = 0; m < 64; m++) { float e = expf(a[m] - mx); a[m] = e; sum += e; }
    float inv = 1.0f / sum;

    float o[16];
#pragma unroll
    for (int d = 0; d < 16; d++) o[d] = 0.f;
    for (int m = 0; m < 64; m++) {
        float am = a[m] * inv;
#pragma unroll
        for (int d = 0; d < 16; d++) o[d] = fmaf(vsm[(h * 16 + d) * 64 + m], am, o[d]);
    }

    int oy = (wr * 8 + yn + 4) & 127;
    int ox = (wc * 8 + xn + 4) & 127;
#pragma unroll
    for (int d = 0; d < 16; d++)
        g_z[((size_t)b * 64 + h * 16 + d) * PX + oy * 128 + ox] = tf32r(o[d]);
}

// ---------------- launcher ---------------------------------------------------
extern "C" void kernel_launch(void* const* d_in, const int* in_sizes, int n_in,
                              void* d_out, int out_size) {
    const float* x           = (const float*)d_in[0];
    const float* temperature = (const float*)d_in[1];
    const float* rel_bias    = (const float*)d_in[2];
    const float* w_high1     = (const float*)d_in[3];
    const float* w_high2     = (const float*)d_in[4];
    const float* w_highout   = (const float*)d_in[5];
    const float* w_qkv       = (const float*)d_in[6];
    const float* w_dwconv    = (const float*)d_in[7];
    const float* w_proj      = (const float*)d_in[8];
    float* out = (float*)d_out;

    static int smem_set = 0;
    if (!smem_set) {
        cudaFuncSetAttribute(k_conv3x3_mma,
            cudaFuncAttributeMaxDynamicSharedMemorySize, 2 * BUF3 * 4);
        cudaFuncSetAttribute(k_conv1x1_pair,
            cudaFuncAttributeMaxDynamicSharedMemorySize, 2 * BUF1 * 4);
        cudaFuncSetAttribute(k_conv1x1_proj,
            cudaFuncAttributeMaxDynamicSharedMemorySize, 2 * BUF1 * 4);
        cudaFuncSetAttribute(k_attn,
            cudaFuncAttributeMaxDynamicSharedMemorySize, ATTN_SMEM_WORDS * 4);
        smem_set = 1;
    }

    int nbDwt  = NSUB / 256;                           // 32768
    int nbPrep = (5 * W3_GROUP + 18432 + 255) / 256;   // 792
    dim3 g3(8, 8, 40);
    dim3 gpair(PX / 256, 16);
    dim3 gproj(PX / 256, 8);
    int dyn3 = 2 * BUF3 * 4;
    int dyn1 = 2 * BUF1 * 4;
    int dynA = ATTN_SMEM_WORDS * 4;

    // 1. DWT + weight prep (merged)
    k_dwt_prepw<<<nbDwt + nbPrep, 256>>>(x, nbDwt, w_high1, w_highout, w_high2, w_qkv, w_proj);
    // 2. all five grouped 3x3 convs (high1 x2 + highout x3), relu, merged
    k_conv3x3_mma<<<g3, 256, dyn3>>>();
    // 3. qkv (-> t) and high2 (-> filt) 1x1 convs, merged launch
    k_conv1x1_pair<<<gpair, 256, dyn1>>>();
    // 4. attention with fused depthwise (roll fused) -> z
    k_attn<<<2048, 256, dynA>>>(rel_bias, temperature, w_dwconv + 128 * 9);
    // 5. proj 1x1 with fused IDWT -> out
    k_conv1x1_proj<<<gproj, 256, dyn1>>>(out);
}

// round 16
// speedup vs baseline: 1.0661x; 1.0264x over previous
#include <cuda_runtime.h>
#include <cstdint>
#include <math.h>

#define BB 8
#define CC 64
#define H2 128
#define W2 128
#define PX (H2*W2)          // 16384
#define NSUB (BB*CC*PX)     // 8388608

// conv3x3 smem image: [ci][18 rows][24 cols], col c <-> gx = tx*16-4+c
#define ROW_STR 24
#define CI_STR 440          // 432 padded to 440 (mod 32 = 24 -> tg banks {0,24,16,8})
#define IMG3 3520           // 8 * CI_STR
#define WCH3 4608           // weights per chunk: 9*64*8
#define BUF3 (IMG3 + WCH3)  // 8128 words per buffer

#define IN1_STR 264
#define W_STR 72
#define BUF1 5376

#define W3_GROUP 36864      // 8 chunks * 4608
#define W1_H2_OFF 0
#define W1_QKV_OFF 9216
#define W1_PROJ_OFF 13824

// ---------------- scratch (device globals; no runtime allocation) -----------
__device__ float g_ll[NSUB];
__device__ float g_lh[NSUB];
__device__ float g_hl[NSUB];
__device__ float g_hh[NSUB];
__device__ float g_h1[2*NSUB];
__device__ float g_filt[NSUB];
__device__ float g_t[NSUB];
__device__ float g_z[NSUB];
__device__ float g_yh[3*NSUB];
__device__ float g_w3[5*W3_GROUP];
__device__ float g_w1[18432];

// ---------------- helpers ----------------------------------------------------
__device__ __forceinline__ unsigned f2tf(float f) {
    unsigned u;
    asm("cvt.rna.tf32.f32 %0, %1;" : "=r"(u) : "f"(f));
    return u;
}
__device__ __forceinline__ float tf32r(float f) { return __uint_as_float(f2tf(f)); }

#define MMA_TF32(c0,c1,c2,c3,a0,a1,a2,a3,b0,b1)                                \
    asm volatile("mma.sync.aligned.m16n8k8.row.col.f32.tf32.tf32.f32 "          \
        "{%0,%1,%2,%3}, {%4,%5,%6,%7}, {%8,%9}, {%0,%1,%2,%3};\n"               \
        : "+f"(c0), "+f"(c1), "+f"(c2), "+f"(c3)                                \
        : "r"(a0), "r"(a1), "r"(a2), "r"(a3), "r"(b0), "r"(b1))

#define CP16(dst, src) \
    asm volatile("cp.async.ca.shared.global [%0], [%1], 16;\n" :: "r"(dst), "l"(src))
#define CP16Z(dst, src, sz) \
    asm volatile("cp.async.ca.shared.global [%0], [%1], 16, %2;\n" :: "r"(dst), "l"(src), "r"(sz))
#define CP_COMMIT()  asm volatile("cp.async.commit_group;\n")
#define CP_WAIT0()   asm volatile("cp.async.wait_group 0;\n" ::: "memory")

// ---------------- merged DWT + weight prep -----------------------------------
// blocks [0, nbDwt): Haar DWT (tf32-rounded). blocks [nbDwt, ...): weight prep.
__global__ void k_dwt_prepw(const float* __restrict__ x, int nbDwt,
                            const float* __restrict__ w_high1,
                            const float* __restrict__ w_highout,
                            const float* __restrict__ w_high2,
                            const float* __restrict__ w_qkv,
                            const float* __restrict__ w_proj) {
    if (blockIdx.x < (unsigned)nbDwt) {
        int idx = blockIdx.x * 256 + threadIdx.x;
        int j  = idx & 127;
        int i  = (idx >> 7) & 127;
        int bc = idx >> 14;
        const float* xp = x + ((size_t)bc * 256 + 2 * i) * 256 + 2 * j;
        float2 t0 = *(const float2*)xp;
        float2 t1 = *(const float2*)(xp + 256);
        float a = t0.x, b = t0.y, c = t1.x, d = t1.y;
        g_ll[idx] = tf32r((a + b + c + d) * 0.5f);
        g_lh[idx] = tf32r((a - b + c - d) * 0.5f);
        g_hl[idx] = tf32r((a + b - c - d) * 0.5f);
        g_hh[idx] = tf32r((a - b - c + d) * 0.5f);
        return;
    }
    int idx = (blockIdx.x - nbDwt) * 256 + threadIdx.x;
    const int total3 = 5 * W3_GROUP;   // 184320
    if (idx < total3) {
        // layout per group/chunk: word = (d*64 + o)*8 + 2*slot + par
        //   slot = ((ci&3) + (o>>2)) & 3, par = ci>>2
        int g = idx / W3_GROUP, r = idx - g * W3_GROUP;
        int ch = r / WCH3;  int w = r - ch * WCH3;
        int d = w / 512;    int rem = w - d * 512;
        int o = rem >> 3;   int s = rem & 7;
        int slot = s >> 1, par = s & 1;
        int ci = par * 4 + ((slot - (o >> 2)) & 3);
        const float* src = (g < 2) ? (w_high1 + g * 36864)
                                   : (w_highout + (g - 2) * 36864);
        float v = src[((size_t)o * 64 + ch * 8 + ci) * 9 + d];
        g_w3[idx] = tf32r(v);
    }
    int i1 = idx - total3;
    if (i1 >= 0 && i1 < 18432) {
        float v = 0.f;
        if (i1 < 9216) {               // high2: KC=128
            int ch = i1 / 1152, r = i1 - ch * 1152;
            int ci = r / 72, o = r - ci * 72;
            if (o < 64) v = w_high2[(size_t)o * 128 + ch * 16 + ci];
        } else if (i1 < 13824) {       // qkv v-slice: KC=64
            int r2 = i1 - 9216;
            int ch = r2 / 1152, r = r2 - ch * 1152;
            int ci = r / 72, o = r - ci * 72;
            if (o < 64) v = w_qkv[128 * 64 + (size_t)o * 64 + ch * 16 + ci];
        } else {                       // proj: KC=64
            int r2 = i1 - 13824;
            int ch = r2 / 1152, r = r2 - ch * 1152;
            int ci = r / 72, o = r - ci * 72;
            if (o < 64) v = w_proj[(size_t)o * 64 + ch * 16 + ci];
        }
        g_w1[i1] = tf32r(v);
    }
}

// ---------------- merged 3x3 convs, tf32 MMA, 2m x 4n warp tiling ------------
// grid (8,8,40): z: grp = z>>3, b = z&7.
// grp: 0 lh->h1[0:64], 1 hl->h1[64:128], 2 lh->yh[0:64], 3 hl->yh[64:128],
//      4 hh->yh[128:192]. All relu.
__global__ void __launch_bounds__(256, 2) k_conv3x3_mma() {
    extern __shared__ unsigned sm3[];
    int tx = blockIdx.x, ty = blockIdx.y;
    int bz = blockIdx.z;
    int grp = bz >> 3, b = bz & 7;

    const float* in;
    float* out;
    int ostr;
    if (grp == 0)      { in = g_lh; out = g_h1;                      ostr = 128 * PX; }
    else if (grp == 1) { in = g_hl; out = g_h1 + (size_t)64 * PX;    ostr = 128 * PX; }
    else if (grp == 2) { in = g_lh; out = g_yh;                      ostr = 192 * PX; }
    else if (grp == 3) { in = g_hl; out = g_yh + (size_t)64 * PX;    ostr = 192 * PX; }
    else               { in = g_hh; out = g_yh + (size_t)128 * PX;   ostr = 192 * PX; }
    const float* wsc = g_w3 + (size_t)grp * W3_GROUP;

    int tid  = threadIdx.x;
    int wp   = tid >> 5;
    int lane = tid & 31;
    int gid  = lane >> 2, tg = lane & 3;
    int mh = wp & 1;          // m half: tiles {mh*32, mh*32+16}
    int nq = wp >> 1;         // n quarter: 64 px
    int gy0  = ty * 16 - 1;
    int gx0s = tx * 16 - 4;
    unsigned smaddr = (unsigned)__cvta_generic_to_shared(sm3);
    const float* ib0 = in + (size_t)b * 64 * PX;

    int posB[8];
#pragma unroll
    for (int nt = 0; nt < 8; nt++) {
        int n = nq * 64 + nt * 8 + gid;
        posB[nt] = (n >> 4) * ROW_STR + (n & 15) + 3;
    }

    float acc[2][8][4];
#pragma unroll
    for (int mt = 0; mt < 2; mt++)
#pragma unroll
        for (int t = 0; t < 8; t++) {
            acc[mt][t][0] = acc[mt][t][1] = acc[mt][t][2] = acc[mt][t][3] = 0.f;
        }

    // image: 8 ci x 18 rows x 6 segments of 4 floats (16B each) = 864 copies
#define STAGE3(CH) {                                                            \
    int c8 = (CH);                                                              \
    unsigned base3 = smaddr + (unsigned)((c8 & 1) * BUF3) * 4u;                 \
    const float* ib = ib0 + (size_t)c8 * 8 * PX;                                \
    for (int l = tid; l < 864; l += 256) {                                      \
        int ciL = l / 108, rr = l - ciL * 108;                                  \
        int row = rr / 6, s = rr - row * 6;                                     \
        int gy = gy0 + row;                                                     \
        int gxs = gx0s + s * 4;                                                 \
        bool ok = ((unsigned)gy < 128u) && ((unsigned)gxs <= 124u);             \
        const float* srcp = ib + (size_t)ciL * PX + (ok ? (gy * 128 + gxs) : 0);\
        int sz = ok ? 16 : 0;                                                   \
        CP16Z(base3 + (unsigned)(ciL * CI_STR + row * ROW_STR + s * 4) * 4u,    \
              srcp, sz);                                                        \
    }                                                                           \
    const float4* ws3 = (const float4*)(wsc + (size_t)c8 * WCH3);               \
    unsigned wb3 = base3 + (unsigned)IMG3 * 4u;                                 \
    for (int l = tid; l < 1152; l += 256)                                       \
        CP16(wb3 + (unsigned)l * 16u, ws3 + l);                                 \
    CP_COMMIT(); }

    STAGE3(0);
    int t0 = mh * 32;
    int s0 = (tg + ((t0 + gid) >> 2)) & 3;   // slot for rows o, o+16
    int s8 = (s0 + 2) & 3;                   // slot for rows o+8, o+24

    for (int ch = 0; ch < 8; ch++) {
        CP_WAIT0();
        __syncthreads();
        if (ch < 7) STAGE3(ch + 1);

        const unsigned* bufc = sm3 + (ch & 1) * BUF3;
        const unsigned* w_s  = bufc + IMG3;
#pragma unroll
        for (int d = 0; d < 9; d++) {
            const unsigned* ap = w_s + (d * 64 + t0 + gid) * 8;
            uint2 A0  = *(const uint2*)(ap + 2 * s0);          // rows o     : k tg, tg+4
            uint2 A8  = *(const uint2*)(ap + 64 + 2 * s8);     // rows o+8
            uint2 A16 = *(const uint2*)(ap + 128 + 2 * s0);    // rows o+16
            uint2 A24 = *(const uint2*)(ap + 192 + 2 * s8);    // rows o+24
            int dOff = (d / 3) * ROW_STR + (d % 3);
            const unsigned* bw = bufc + tg * CI_STR + dOff;
#pragma unroll
            for (int nt = 0; nt < 8; nt++) {
                unsigned b0 = bw[posB[nt]];
                unsigned b1 = bw[posB[nt] + 4 * CI_STR];
                MMA_TF32(acc[0][nt][0], acc[0][nt][1], acc[0][nt][2], acc[0][nt][3],
                         A0.x, A8.x, A0.y, A8.y, b0, b1);
                MMA_TF32(acc[1][nt][0], acc[1][nt][1], acc[1][nt][2], acc[1][nt][3],
                         A16.x, A24.x, A16.y, A24.y, b0, b1);
            }
        }
    }
#undef STAGE3

    float* ob = out + (size_t)b * ostr;
#pragma unroll
    for (int mt = 0; mt < 2; mt++) {
        int o = mh * 32 + mt * 16 + gid;
#pragma unroll
        for (int nt = 0; nt < 8; nt++) {
            int n = nq * 64 + nt * 8 + tg * 2;
            int gy = ty * 16 + (n >> 4), gx = tx * 16 + (n & 15);
            float* p0 = ob + (size_t)o * PX + gy * 128 + gx;
            *(float2*)p0 = make_float2(tf32r(fmaxf(acc[mt][nt][0], 0.f)),
                                       tf32r(fmaxf(acc[mt][nt][1], 0.f)));
            float* p1 = p0 + 8 * PX;
            *(float2*)p1 = make_float2(tf32r(fmaxf(acc[mt][nt][2], 0.f)),
                                       tf32r(fmaxf(acc[mt][nt][3], 0.f)));
        }
    }
}

// ---------------- 1x1 conv body, tf32 MMA, 2-stage pipeline ------------------
// mode: 0 = plain, 1 = relu, 2 = fused IDWT epilogue (out = final 256x256, aux = yh)
__device__ __forceinline__ void conv1x1_body(
        const float* __restrict__ in, float* __restrict__ out,
        const float* __restrict__ wsc, int nch, int inBstride, int mode,
        const float* __restrict__ aux, int b, unsigned* sm1) {
    int p0blk = blockIdx.x * 256;
    int tid  = threadIdx.x;
    int wp   = tid >> 5;
    int lane = tid & 31;
    int gid  = lane >> 2, tg = lane & 3;
    int mh = wp & 1;
    int nq = wp >> 1;
    unsigned smaddr = (unsigned)__cvta_generic_to_shared(sm1);
    const float* ib = in + (size_t)b * inBstride + p0blk;

    float acc[2][8][4];
#pragma unroll
    for (int mt = 0; mt < 2; mt++)
#pragma unroll
        for (int t = 0; t < 8; t++) {
            acc[mt][t][0] = acc[mt][t][1] = acc[mt][t][2] = acc[mt][t][3] = 0.f;
        }

#define STAGE1(CH) {                                                            \
    int c8 = (CH);                                                              \
    unsigned base1 = smaddr + (unsigned)((c8 & 1) * BUF1) * 4u;                 \
    for (int l = tid; l < 1024; l += 256) {                                     \
        int ciL = l >> 6, p4 = l & 63;                                          \
        const float4* srcp = (const float4*)(ib + (size_t)(c8 * 16 + ciL) * PX) + p4; \
        CP16(base1 + (unsigned)(ciL * IN1_STR + p4 * 4) * 4u, srcp);            \
    }                                                                           \
    const float4* ws1 = (const float4*)(wsc + (size_t)c8 * 1152);               \
    unsigned wb1 = base1 + 4224u * 4u;                                          \
    for (int l = tid; l < 288; l += 256)                                        \
        CP16(wb1 + (unsigned)l * 16u, ws1 + l);                                 \
    CP_COMMIT(); }

    STAGE1(0);
    for (int ch = 0; ch < nch; ch++) {
        CP_WAIT0();
        __syncthreads();
        if (ch + 1 < nch) STAGE1(ch + 1);

        const unsigned* bufc = sm1 + (ch & 1) * BUF1;
        const unsigned* w_s  = bufc + 4224;
#pragma unroll
        for (int ks = 0; ks < 2; ks++) {
            const unsigned* aw  = w_s + (ks * 8 + tg) * W_STR + mh * 32 + gid;
            const unsigned* aw4 = aw + 4 * W_STR;
            unsigned a0  = aw[0],  a1  = aw[8],  a2  = aw4[0],  a3  = aw4[8];
            unsigned a0b = aw[16], a1b = aw[24], a2b = aw4[16], a3b = aw4[24];
            const unsigned* bw = bufc + (ks * 8 + tg) * IN1_STR + nq * 64;
#pragma unroll
            for (int nt = 0; nt < 8; nt++) {
                unsigned b0 = bw[nt * 8 + gid];
                unsigned b1 = bw[4 * IN1_STR + nt * 8 + gid];
                MMA_TF32(acc[0][nt][0], acc[0][nt][1], acc[0][nt][2], acc[0][nt][3],
                         a0, a1, a2, a3, b0, b1);
                MMA_TF32(acc[1][nt][0], acc[1][nt][1], acc[1][nt][2], acc[1][nt][3],
                         a0b, a1b, a2b, a3b, b0, b1);
            }
        }
    }
#undef STAGE1

    if (mode != 2) {
        float* ob = out + (size_t)b * 64 * PX + p0blk;
#pragma unroll
        for (int mt = 0; mt < 2; mt++) {
            int o = mh * 32 + mt * 16 + gid;
#pragma unroll
            for (int nt = 0; nt < 8; nt++) {
                int n = nq * 64 + nt * 8 + tg * 2;
                float2 r0 = make_float2(acc[mt][nt][0], acc[mt][nt][1]);
                float2 r1 = make_float2(acc[mt][nt][2], acc[mt][nt][3]);
                if (mode == 1) {
                    r0.x = fmaxf(r0.x, 0.f); r0.y = fmaxf(r0.y, 0.f);
                    r1.x = fmaxf(r1.x, 0.f); r1.y = fmaxf(r1.y, 0.f);
                }
                *(float2*)(ob + (size_t)o * PX + n)       = r0;
                *(float2*)(ob + (size_t)(o + 8) * PX + n) = r1;
            }
        }
    } else {
        // fused IDWT: ll = acc (proj output), lh/hl/hh from aux (= g_yh)
        const float* yb = aux + (size_t)b * 192 * PX;
        float* ob2 = out + (size_t)b * 64 * 65536;
#pragma unroll
        for (int mt = 0; mt < 2; mt++) {
#pragma unroll
            for (int nt = 0; nt < 8; nt++) {
                int n = nq * 64 + nt * 8 + tg * 2;
                int p = p0blk + n;
                int i = p >> 7, j = p & 127;
#pragma unroll
                for (int half = 0; half < 2; half++) {
                    int c = mh * 32 + mt * 16 + gid + half * 8;
                    float ll0 = acc[mt][nt][half * 2];
                    float ll1 = acc[mt][nt][half * 2 + 1];
                    const float* yc = yb + (size_t)c * PX + p;
                    float2 lh = *(const float2*)yc;
                    float2 hl = *(const float2*)(yc + (size_t)64 * PX);
                    float2 hh = *(const float2*)(yc + (size_t)128 * PX);
                    float4 top, bot;
                    top.x = (ll0 + lh.x + hl.x + hh.x) * 0.5f;
                    top.y = (ll0 - lh.x + hl.x - hh.x) * 0.5f;
                    bot.x = (ll0 + lh.x - hl.x - hh.x) * 0.5f;
                    bot.y = (ll0 - lh.x - hl.x + hh.x) * 0.5f;
                    top.z = (ll1 + lh.y + hl.y + hh.y) * 0.5f;
                    top.w = (ll1 - lh.y + hl.y - hh.y) * 0.5f;
                    bot.z = (ll1 + lh.y - hl.y - hh.y) * 0.5f;
                    bot.w = (ll1 - lh.y - hl.y + hh.y) * 0.5f;
                    float* op = ob2 + ((size_t)c * 256 + 2 * i) * 256 + 2 * j;
                    *(float4*)op         = top;
                    *(float4*)(op + 256) = bot;
                }
            }
        }
    }
}

// merged qkv + high2 launch: grid (64, 16); y<8 -> qkv(b=y), else high2(b=y-8)
__global__ void __launch_bounds__(256, 2) k_conv1x1_pair() {
    extern __shared__ unsigned smp[];
    int y = blockIdx.y;
    if (y < 8) {
        conv1x1_body(g_ll, g_t, g_w1 + W1_QKV_OFF, 4, 64 * PX, 0, nullptr, y, smp);
    } else {
        conv1x1_body(g_h1, g_filt, g_w1 + W1_H2_OFF, 8, 128 * PX, 1, nullptr, y - 8, smp);
    }
}

// proj (+ fused IDWT): grid (64, 8)
__global__ void __launch_bounds__(256, 2) k_conv1x1_proj(float* __restrict__ out) {
    extern __shared__ unsigned smp[];
    conv1x1_body(g_z, out, g_w1 + W1_PROJ_OFF, 4, 64 * PX, 2, g_yh, blockIdx.y, smp);
}

// ---------------- window attention + fused depthwise 3x3 ---------------------
// dynamic smem: qs[4096] vsm[4096] tp[6400] scl[256] tbl[900] stemp[4] sdw[576]
#define ATTN_SMEM_WORDS 16328
__global__ void __launch_bounds__(256) k_attn(
        const float* __restrict__ table, const float* __restrict__ temp,
        const float* __restrict__ wdw) {
    extern __shared__ float sA[];
    float* qs    = sA;
    float* vsm   = sA + 4096;
    float* tp    = sA + 8192;
    float* scl   = sA + 14592;
    float* tbl   = sA + 14848;
    float* stemp = sA + 15748;
    float* sdw   = sA + 15752;

    int bw = blockIdx.x;
    int b  = bw >> 8;
    int wr = (bw >> 4) & 15;
    int wc = bw & 15;
    int tid = threadIdx.x;

    if (tid < 4) stemp[tid] = temp[tid];
    for (int l = tid; l < 900; l += 256) tbl[l] = table[l];
    for (int l = tid; l < 576; l += 256) sdw[l] = wdw[l];

    // t-patch (10x10 per channel) for depthwise
    for (int l = tid; l < 6400; l += 256) {
        int c = l / 100, p = l - c * 100;
        int py = p / 10, px = p - py * 10;
        int gy = wr * 8 - 1 + py, gx = wc * 8 - 1 + px;
        float v = 0.f;
        if ((unsigned)gy < 128u && (unsigned)gx < 128u)
            v = g_t[((size_t)b * 64 + c) * PX + gy * 128 + gx];
        tp[l] = v;
    }
    // q (shifted ll)
    for (int l = tid; l < 4096; l += 256) {
        int c = l >> 6, n = l & 63;
        int y = n >> 3, x = n & 7;
        int qy = (wr * 8 + y + 4) & 127;
        int qx = (wc * 8 + x + 4) & 127;
        qs[l] = g_ll[((size_t)b * 64 + c) * PX + qy * 128 + qx];
    }
    __syncthreads();

    // depthwise + filt -> vsm
    for (int l = tid; l < 4096; l += 256) {
        int c = l >> 6, n = l & 63;
        int y = n >> 3, x = n & 7;
        const float* tc = tp + c * 100;
        const float* wc9 = sdw + c * 9;
        float a0 = 0.f;
#pragma unroll
        for (int dy = 0; dy < 3; dy++)
#pragma unroll
            for (int dx = 0; dx < 3; dx++)
                a0 = fmaf(wc9[dy * 3 + dx], tc[(y + dy) * 10 + x + dx], a0);
        float ft = g_filt[((size_t)b * 64 + c) * PX + (wr * 8 + y) * 128 + wc * 8 + x];
        vsm[l] = a0 * (1.0f + ft);
    }
    __syncthreads();

    {
        int h = tid >> 6, n = tid & 63;
        float s = 0.f;
#pragma unroll
        for (int d = 0; d < 16; d++) { float v = qs[(h * 16 + d) * 64 + n]; s += v * v; }
        float r = rsqrtf(s);
        scl[tid] = (s > 1e-24f) ? r : 1e12f;
    }
    __syncthreads();

    int h = tid >> 6, n = tid & 63;
    int yn = n >> 3, xn = n & 7;
    float myscl = scl[tid];
    float tph = stemp[h];

    float qn[16];
#pragma unroll
    for (int d = 0; d < 16; d++) qn[d] = qs[(h * 16 + d) * 64 + n] * myscl;

    float a[64];
#pragma unroll
    for (int m4 = 0; m4 < 64; m4 += 4) {
        float4 s = make_float4(0.f, 0.f, 0.f, 0.f);
#pragma unroll
        for (int d = 0; d < 16; d++) {
            float qd = qn[d];
            float4 qv = *(const float4*)&qs[(h * 16 + d) * 64 + m4];
            s.x = fmaf(qd, qv.x, s.x);
            s.y = fmaf(qd, qv.y, s.y);
            s.z = fmaf(qd, qv.z, s.z);
            s.w = fmaf(qd, qv.w, s.w);
        }
        float4 sc = *(const float4*)&scl[(h << 6) + m4];
#pragma unroll
        for (int q = 0; q < 4; q++) {
            int m = m4 + q;
            int ym = m >> 3, xm = m & 7;
            int ridx = (yn - ym + 7) * 15 + (xn - xm + 7);
            float sv = (q == 0 ? s.x : q == 1 ? s.y : q == 2 ? s.z : s.w);
            float scv = (q == 0 ? sc.x : q == 1 ? sc.y : q == 2 ? sc.z : sc.w);
            a[m] = (sv * scv + tbl[ridx * 4 + h]) * tph;
        }
    }

    float mx = -1e30f;
#pragma unroll
    for (int m = 0; m < 64; m++) mx = fmaxf(mx, a[m]);
    float sum = 0.f;
#pragma unroll
    for (int m = 0; m < 64; m++) { float e = __expf(a[m] - mx); a[m] = e; sum += e; }
    float inv = 1.0f / sum;

    float o[16];
#pragma unroll
    for (int d = 0; d < 16; d++) o[d] = 0.f;
#pragma unroll
    for (int m4 = 0; m4 < 64; m4 += 4) {
        float am0 = a[m4] * inv, am1 = a[m4 + 1] * inv;
        float am2 = a[m4 + 2] * inv, am3 = a[m4 + 3] * inv;
#pragma unroll
        for (int d = 0; d < 16; d++) {
            float4 vv = *(const float4*)&vsm[(h * 16 + d) * 64 + m4];
            float od = o[d];
            od = fmaf(vv.x, am0, od);
            od = fmaf(vv.y, am1, od);
            od = fmaf(vv.z, am2, od);
            od = fmaf(vv.w, am3, od);
            o[d] = od;
        }
    }

    int oy = (wr * 8 + yn + 4) & 127;
    int ox = (wc * 8 + xn + 4) & 127;
#pragma unroll
    for (int d = 0; d < 16; d++)
        g_z[((size_t)b * 64 + h * 16 + d) * PX + oy * 128 + ox] = tf32r(o[d]);
}

// ---------------- launcher ---------------------------------------------------
extern "C" void kernel_launch(void* const* d_in, const int* in_sizes, int n_in,
                              void* d_out, int out_size) {
    const float* x           = (const float*)d_in[0];
    const float* temperature = (const float*)d_in[1];
    const float* rel_bias    = (const float*)d_in[2];
    const float* w_high1     = (const float*)d_in[3];
    const float* w_high2     = (const float*)d_in[4];
    const float* w_highout   = (const float*)d_in[5];
    const float* w_qkv       = (const float*)d_in[6];
    const float* w_dwconv    = (const float*)d_in[7];
    const float* w_proj      = (const float*)d_in[8];
    float* out = (float*)d_out;

    static int smem_set = 0;
    if (!smem_set) {
        cudaFuncSetAttribute(k_conv3x3_mma,
            cudaFuncAttributeMaxDynamicSharedMemorySize, 2 * BUF3 * 4);
        cudaFuncSetAttribute(k_conv1x1_pair,
            cudaFuncAttributeMaxDynamicSharedMemorySize, 2 * BUF1 * 4);
        cudaFuncSetAttribute(k_conv1x1_proj,
            cudaFuncAttributeMaxDynamicSharedMemorySize, 2 * BUF1 * 4);
        cudaFuncSetAttribute(k_attn,
            cudaFuncAttributeMaxDynamicSharedMemorySize, ATTN_SMEM_WORDS * 4);
        smem_set = 1;
    }

    int nbDwt  = NSUB / 256;                           // 32768
    int nbPrep = (5 * W3_GROUP + 18432 + 255) / 256;   // 792
    dim3 g3(8, 8, 40);
    dim3 gpair(PX / 256, 16);
    dim3 gproj(PX / 256, 8);
    int dyn3 = 2 * BUF3 * 4;
    int dyn1 = 2 * BUF1 * 4;
    int dynA = ATTN_SMEM_WORDS * 4;

    // 1. DWT + weight prep (merged)
    k_dwt_prepw<<<nbDwt + nbPrep, 256>>>(x, nbDwt, w_high1, w_highout, w_high2, w_qkv, w_proj);
    // 2. all five grouped 3x3 convs (high1 x2 + highout x3), relu, merged
    k_conv3x3_mma<<<g3, 256, dyn3>>>();
    // 3. qkv (-> t) and high2 (-> filt) 1x1 convs, merged launch
    k_conv1x1_pair<<<gpair, 256, dyn1>>>();
    // 4. attention with fused depthwise (roll fused) -> z
    k_attn<<<2048, 256, dynA>>>(rel_bias, temperature, w_dwconv + 128 * 9);
    // 5. proj 1x1 with fused IDWT -> out
    k_conv1x1_proj<<<gproj, 256, dyn1>>>(out);
}

// round 17
// speedup vs baseline: 1.1005x; 1.0323x over previous
#include <cuda_runtime.h>
#include <cstdint>
#include <math.h>

#define BB 8
#define CC 64
#define H2 128
#define W2 128
#define PX (H2*W2)          // 16384
#define NSUB (BB*CC*PX)     // 8388608

// conv3x3 smem image: [ci][18 rows][24 cols], col c <-> gx = tx*16-4+c
#define ROW_STR 24
#define CI_STR 440          // 432 padded to 440 (mod 32 = 24 -> tg banks {0,24,16,8})
#define IMG3 3520           // 8 * CI_STR
#define WCH3 4608           // weights per chunk: 9*64*8
#define BUF3 (IMG3 + WCH3)  // 8128 words per buffer

#define IN1_STR 264
#define W_STR 72
#define BUF1 5376

#define W3_GROUP 36864      // 8 chunks * 4608
#define W1_H2_OFF 0
#define W1_QKV_OFF 9216
#define W1_PROJ_OFF 13824

// ---------------- scratch (device globals; no runtime allocation) -----------
__device__ float g_ll[NSUB];
__device__ float g_lh[NSUB];
__device__ float g_hl[NSUB];
__device__ float g_hh[NSUB];
__device__ float g_h1[2*NSUB];
__device__ float g_filt[NSUB];
__device__ float g_t[NSUB];
__device__ float g_z[NSUB];
__device__ float g_yh[3*NSUB];
__device__ float g_w3[5*W3_GROUP];
__device__ float g_w1[18432];

// ---------------- helpers ----------------------------------------------------
__device__ __forceinline__ unsigned f2tf(float f) {
    unsigned u;
    asm("cvt.rna.tf32.f32 %0, %1;" : "=r"(u) : "f"(f));
    return u;
}
__device__ __forceinline__ float tf32r(float f) { return __uint_as_float(f2tf(f)); }

#define MMA_TF32(c0,c1,c2,c3,a0,a1,a2,a3,b0,b1)                                \
    asm volatile("mma.sync.aligned.m16n8k8.row.col.f32.tf32.tf32.f32 "          \
        "{%0,%1,%2,%3}, {%4,%5,%6,%7}, {%8,%9}, {%0,%1,%2,%3};\n"               \
        : "+f"(c0), "+f"(c1), "+f"(c2), "+f"(c3)                                \
        : "r"(a0), "r"(a1), "r"(a2), "r"(a3), "r"(b0), "r"(b1))

#define CP16(dst, src) \
    asm volatile("cp.async.ca.shared.global [%0], [%1], 16;\n" :: "r"(dst), "l"(src))
#define CP16Z(dst, src, sz) \
    asm volatile("cp.async.ca.shared.global [%0], [%1], 16, %2;\n" :: "r"(dst), "l"(src), "r"(sz))
#define CP_COMMIT()  asm volatile("cp.async.commit_group;\n")
#define CP_WAIT0()   asm volatile("cp.async.wait_group 0;\n" ::: "memory")

// ---------------- merged DWT + weight prep -----------------------------------
__global__ void k_dwt_prepw(const float* __restrict__ x, int nbDwt,
                            const float* __restrict__ w_high1,
                            const float* __restrict__ w_highout,
                            const float* __restrict__ w_high2,
                            const float* __restrict__ w_qkv,
                            const float* __restrict__ w_proj) {
    if (blockIdx.x < (unsigned)nbDwt) {
        int idx = blockIdx.x * 256 + threadIdx.x;
        int j  = idx & 127;
        int i  = (idx >> 7) & 127;
        int bc = idx >> 14;
        const float* xp = x + ((size_t)bc * 256 + 2 * i) * 256 + 2 * j;
        float2 t0 = *(const float2*)xp;
        float2 t1 = *(const float2*)(xp + 256);
        float a = t0.x, b = t0.y, c = t1.x, d = t1.y;
        g_ll[idx] = tf32r((a + b + c + d) * 0.5f);
        g_lh[idx] = tf32r((a - b + c - d) * 0.5f);
        g_hl[idx] = tf32r((a + b - c - d) * 0.5f);
        g_hh[idx] = tf32r((a - b - c + d) * 0.5f);
        return;
    }
    int idx = (blockIdx.x - nbDwt) * 256 + threadIdx.x;
    const int total3 = 5 * W3_GROUP;   // 184320
    if (idx < total3) {
        int g = idx / W3_GROUP, r = idx - g * W3_GROUP;
        int ch = r / WCH3;  int w = r - ch * WCH3;
        int d = w / 512;    int rem = w - d * 512;
        int o = rem >> 3;   int s = rem & 7;
        int slot = s >> 1, par = s & 1;
        int ci = par * 4 + ((slot - (o >> 2)) & 3);
        const float* src = (g < 2) ? (w_high1 + g * 36864)
                                   : (w_highout + (g - 2) * 36864);
        float v = src[((size_t)o * 64 + ch * 8 + ci) * 9 + d];
        g_w3[idx] = tf32r(v);
    }
    int i1 = idx - total3;
    if (i1 >= 0 && i1 < 18432) {
        float v = 0.f;
        if (i1 < 9216) {               // high2: KC=128
            int ch = i1 / 1152, r = i1 - ch * 1152;
            int ci = r / 72, o = r - ci * 72;
            if (o < 64) v = w_high2[(size_t)o * 128 + ch * 16 + ci];
        } else if (i1 < 13824) {       // qkv v-slice: KC=64
            int r2 = i1 - 9216;
            int ch = r2 / 1152, r = r2 - ch * 1152;
            int ci = r / 72, o = r - ci * 72;
            if (o < 64) v = w_qkv[128 * 64 + (size_t)o * 64 + ch * 16 + ci];
        } else {                       // proj: KC=64
            int r2 = i1 - 13824;
            int ch = r2 / 1152, r = r2 - ch * 1152;
            int ci = r / 72, o = r - ci * 72;
            if (o < 64) v = w_proj[(size_t)o * 64 + ch * 16 + ci];
        }
        g_w1[i1] = tf32r(v);
    }
}

// ---------------- merged 3x3 convs, tf32 MMA, 2m x 4n warp tiling ------------
__global__ void __launch_bounds__(256, 2) k_conv3x3_mma() {
    extern __shared__ unsigned sm3[];
    int tx = blockIdx.x, ty = blockIdx.y;
    int bz = blockIdx.z;
    int grp = bz >> 3, b = bz & 7;

    const float* in;
    float* out;
    int ostr;
    if (grp == 0)      { in = g_lh; out = g_h1;                      ostr = 128 * PX; }
    else if (grp == 1) { in = g_hl; out = g_h1 + (size_t)64 * PX;    ostr = 128 * PX; }
    else if (grp == 2) { in = g_lh; out = g_yh;                      ostr = 192 * PX; }
    else if (grp == 3) { in = g_hl; out = g_yh + (size_t)64 * PX;    ostr = 192 * PX; }
    else               { in = g_hh; out = g_yh + (size_t)128 * PX;   ostr = 192 * PX; }
    const float* wsc = g_w3 + (size_t)grp * W3_GROUP;

    int tid  = threadIdx.x;
    int wp   = tid >> 5;
    int lane = tid & 31;
    int gid  = lane >> 2, tg = lane & 3;
    int mh = wp & 1;
    int nq = wp >> 1;
    int gy0  = ty * 16 - 1;
    int gx0s = tx * 16 - 4;
    unsigned smaddr = (unsigned)__cvta_generic_to_shared(sm3);
    const float* ib0 = in + (size_t)b * 64 * PX;

    int posB[8];
#pragma unroll
    for (int nt = 0; nt < 8; nt++) {
        int n = nq * 64 + nt * 8 + gid;
        posB[nt] = (n >> 4) * ROW_STR + (n & 15) + 3;
    }

    float acc[2][8][4];
#pragma unroll
    for (int mt = 0; mt < 2; mt++)
#pragma unroll
        for (int t = 0; t < 8; t++) {
            acc[mt][t][0] = acc[mt][t][1] = acc[mt][t][2] = acc[mt][t][3] = 0.f;
        }

#define STAGE3(CH) {                                                            \
    int c8 = (CH);                                                              \
    unsigned base3 = smaddr + (unsigned)((c8 & 1) * BUF3) * 4u;                 \
    const float* ib = ib0 + (size_t)c8 * 8 * PX;                                \
    for (int l = tid; l < 864; l += 256) {                                      \
        int ciL = l / 108, rr = l - ciL * 108;                                  \
        int row = rr / 6, s = rr - row * 6;                                     \
        int gy = gy0 + row;                                                     \
        int gxs = gx0s + s * 4;                                                 \
        bool ok = ((unsigned)gy < 128u) && ((unsigned)gxs <= 124u);             \
        const float* srcp = ib + (size_t)ciL * PX + (ok ? (gy * 128 + gxs) : 0);\
        int sz = ok ? 16 : 0;                                                   \
        CP16Z(base3 + (unsigned)(ciL * CI_STR + row * ROW_STR + s * 4) * 4u,    \
              srcp, sz);                                                        \
    }                                                                           \
    const float4* ws3 = (const float4*)(wsc + (size_t)c8 * WCH3);               \
    unsigned wb3 = base3 + (unsigned)IMG3 * 4u;                                 \
    for (int l = tid; l < 1152; l += 256)                                       \
        CP16(wb3 + (unsigned)l * 16u, ws3 + l);                                 \
    CP_COMMIT(); }

    STAGE3(0);
    int t0 = mh * 32;
    int s0 = (tg + ((t0 + gid) >> 2)) & 3;
    int s8 = (s0 + 2) & 3;

    for (int ch = 0; ch < 8; ch++) {
        CP_WAIT0();
        __syncthreads();
        if (ch < 7) STAGE3(ch + 1);

        const unsigned* bufc = sm3 + (ch & 1) * BUF3;
        const unsigned* w_s  = bufc + IMG3;
#pragma unroll
        for (int d = 0; d < 9; d++) {
            const unsigned* ap = w_s + (d * 64 + t0 + gid) * 8;
            uint2 A0  = *(const uint2*)(ap + 2 * s0);
            uint2 A8  = *(const uint2*)(ap + 64 + 2 * s8);
            uint2 A16 = *(const uint2*)(ap + 128 + 2 * s0);
            uint2 A24 = *(const uint2*)(ap + 192 + 2 * s8);
            int dOff = (d / 3) * ROW_STR + (d % 3);
            const unsigned* bw = bufc + tg * CI_STR + dOff;
#pragma unroll
            for (int nt = 0; nt < 8; nt++) {
                unsigned b0 = bw[posB[nt]];
                unsigned b1 = bw[posB[nt] + 4 * CI_STR];
                MMA_TF32(acc[0][nt][0], acc[0][nt][1], acc[0][nt][2], acc[0][nt][3],
                         A0.x, A8.x, A0.y, A8.y, b0, b1);
                MMA_TF32(acc[1][nt][0], acc[1][nt][1], acc[1][nt][2], acc[1][nt][3],
                         A16.x, A24.x, A16.y, A24.y, b0, b1);
            }
        }
    }
#undef STAGE3

    float* ob = out + (size_t)b * ostr;
#pragma unroll
    for (int mt = 0; mt < 2; mt++) {
        int o = mh * 32 + mt * 16 + gid;
#pragma unroll
        for (int nt = 0; nt < 8; nt++) {
            int n = nq * 64 + nt * 8 + tg * 2;
            int gy = ty * 16 + (n >> 4), gx = tx * 16 + (n & 15);
            float* p0 = ob + (size_t)o * PX + gy * 128 + gx;
            *(float2*)p0 = make_float2(tf32r(fmaxf(acc[mt][nt][0], 0.f)),
                                       tf32r(fmaxf(acc[mt][nt][1], 0.f)));
            float* p1 = p0 + 8 * PX;
            *(float2*)p1 = make_float2(tf32r(fmaxf(acc[mt][nt][2], 0.f)),
                                       tf32r(fmaxf(acc[mt][nt][3], 0.f)));
        }
    }
}

// ---------------- 1x1 conv body, tf32 MMA, 2-stage pipeline ------------------
__device__ __forceinline__ void conv1x1_body(
        const float* __restrict__ in, float* __restrict__ out,
        const float* __restrict__ wsc, int nch, int inBstride, int mode,
        const float* __restrict__ aux, int b, unsigned* sm1) {
    int p0blk = blockIdx.x * 256;
    int tid  = threadIdx.x;
    int wp   = tid >> 5;
    int lane = tid & 31;
    int gid  = lane >> 2, tg = lane & 3;
    int mh = wp & 1;
    int nq = wp >> 1;
    unsigned smaddr = (unsigned)__cvta_generic_to_shared(sm1);
    const float* ib = in + (size_t)b * inBstride + p0blk;

    float acc[2][8][4];
#pragma unroll
    for (int mt = 0; mt < 2; mt++)
#pragma unroll
        for (int t = 0; t < 8; t++) {
            acc[mt][t][0] = acc[mt][t][1] = acc[mt][t][2] = acc[mt][t][3] = 0.f;
        }

#define STAGE1(CH) {                                                            \
    int c8 = (CH);                                                              \
    unsigned base1 = smaddr + (unsigned)((c8 & 1) * BUF1) * 4u;                 \
    for (int l = tid; l < 1024; l += 256) {                                     \
        int ciL = l >> 6, p4 = l & 63;                                          \
        const float4* srcp = (const float4*)(ib + (size_t)(c8 * 16 + ciL) * PX) + p4; \
        CP16(base1 + (unsigned)(ciL * IN1_STR + p4 * 4) * 4u, srcp);            \
    }                                                                           \
    const float4* ws1 = (const float4*)(wsc + (size_t)c8 * 1152);               \
    unsigned wb1 = base1 + 4224u * 4u;                                          \
    for (int l = tid; l < 288; l += 256)                                        \
        CP16(wb1 + (unsigned)l * 16u, ws1 + l);                                 \
    CP_COMMIT(); }

    STAGE1(0);
    for (int ch = 0; ch < nch; ch++) {
        CP_WAIT0();
        __syncthreads();
        if (ch + 1 < nch) STAGE1(ch + 1);

        const unsigned* bufc = sm1 + (ch & 1) * BUF1;
        const unsigned* w_s  = bufc + 4224;
#pragma unroll
        for (int ks = 0; ks < 2; ks++) {
            const unsigned* aw  = w_s + (ks * 8 + tg) * W_STR + mh * 32 + gid;
            const unsigned* aw4 = aw + 4 * W_STR;
            unsigned a0  = aw[0],  a1  = aw[8],  a2  = aw4[0],  a3  = aw4[8];
            unsigned a0b = aw[16], a1b = aw[24], a2b = aw4[16], a3b = aw4[24];
            const unsigned* bw = bufc + (ks * 8 + tg) * IN1_STR + nq * 64;
#pragma unroll
            for (int nt = 0; nt < 8; nt++) {
                unsigned b0 = bw[nt * 8 + gid];
                unsigned b1 = bw[4 * IN1_STR + nt * 8 + gid];
                MMA_TF32(acc[0][nt][0], acc[0][nt][1], acc[0][nt][2], acc[0][nt][3],
                         a0, a1, a2, a3, b0, b1);
                MMA_TF32(acc[1][nt][0], acc[1][nt][1], acc[1][nt][2], acc[1][nt][3],
                         a0b, a1b, a2b, a3b, b0, b1);
            }
        }
    }
#undef STAGE1

    if (mode != 2) {
        float* ob = out + (size_t)b * 64 * PX + p0blk;
#pragma unroll
        for (int mt = 0; mt < 2; mt++) {
            int o = mh * 32 + mt * 16 + gid;
#pragma unroll
            for (int nt = 0; nt < 8; nt++) {
                int n = nq * 64 + nt * 8 + tg * 2;
                float2 r0 = make_float2(acc[mt][nt][0], acc[mt][nt][1]);
                float2 r1 = make_float2(acc[mt][nt][2], acc[mt][nt][3]);
                if (mode == 1) {
                    r0.x = fmaxf(r0.x, 0.f); r0.y = fmaxf(r0.y, 0.f);
                    r1.x = fmaxf(r1.x, 0.f); r1.y = fmaxf(r1.y, 0.f);
                }
                *(float2*)(ob + (size_t)o * PX + n)       = r0;
                *(float2*)(ob + (size_t)(o + 8) * PX + n) = r1;
            }
        }
    } else {
        const float* yb = aux + (size_t)b * 192 * PX;
        float* ob2 = out + (size_t)b * 64 * 65536;
#pragma unroll
        for (int mt = 0; mt < 2; mt++) {
#pragma unroll
            for (int nt = 0; nt < 8; nt++) {
                int n = nq * 64 + nt * 8 + tg * 2;
                int p = p0blk + n;
                int i = p >> 7, j = p & 127;
#pragma unroll
                for (int half = 0; half < 2; half++) {
                    int c = mh * 32 + mt * 16 + gid + half * 8;
                    float ll0 = acc[mt][nt][half * 2];
                    float ll1 = acc[mt][nt][half * 2 + 1];
                    const float* yc = yb + (size_t)c * PX + p;
                    float2 lh = *(const float2*)yc;
                    float2 hl = *(const float2*)(yc + (size_t)64 * PX);
                    float2 hh = *(const float2*)(yc + (size_t)128 * PX);
                    float4 top, bot;
                    top.x = (ll0 + lh.x + hl.x + hh.x) * 0.5f;
                    top.y = (ll0 - lh.x + hl.x - hh.x) * 0.5f;
                    bot.x = (ll0 + lh.x - hl.x - hh.x) * 0.5f;
                    bot.y = (ll0 - lh.x - hl.x + hh.x) * 0.5f;
                    top.z = (ll1 + lh.y + hl.y + hh.y) * 0.5f;
                    top.w = (ll1 - lh.y + hl.y - hh.y) * 0.5f;
                    bot.z = (ll1 + lh.y - hl.y - hh.y) * 0.5f;
                    bot.w = (ll1 - lh.y - hl.y + hh.y) * 0.5f;
                    float* op = ob2 + ((size_t)c * 256 + 2 * i) * 256 + 2 * j;
                    *(float4*)op         = top;
                    *(float4*)(op + 256) = bot;
                }
            }
        }
    }
}

__global__ void __launch_bounds__(256, 2) k_conv1x1_pair() {
    extern __shared__ unsigned smp[];
    int y = blockIdx.y;
    if (y < 8) {
        conv1x1_body(g_ll, g_t, g_w1 + W1_QKV_OFF, 4, 64 * PX, 0, nullptr, y, smp);
    } else {
        conv1x1_body(g_h1, g_filt, g_w1 + W1_H2_OFF, 8, 128 * PX, 1, nullptr, y - 8, smp);
    }
}

__global__ void __launch_bounds__(256, 2) k_conv1x1_proj(float* __restrict__ out) {
    extern __shared__ unsigned smp[];
    conv1x1_body(g_z, out, g_w1 + W1_PROJ_OFF, 4, 64 * PX, 2, g_yh, blockIdx.y, smp);
}

// ---------------- window attention + fused depthwise 3x3 ---------------------
// Two-pass streaming softmax (no a[64] array) -> low regs -> 4 blocks/SM.
// smem: region A [0,6400) tp then qs[4096]; vsm [6400,10496);
//       scl [10496,10752); tbl [10752,11652); stemp [11652,11656);
//       sdw [11656,12232). Total 12232 words = 48928 B.
#define ATTN_SMEM_WORDS 12232
__global__ void __launch_bounds__(256, 4) k_attn(
        const float* __restrict__ table, const float* __restrict__ temp,
        const float* __restrict__ wdw) {
    extern __shared__ float sA[];
    float* tp    = sA;          // [0,6400) staging for depthwise
    float* qs    = sA;          // [0,4096) after tp is dead
    float* vsm   = sA + 6400;
    float* scl   = sA + 10496;
    float* tbl   = sA + 10752;
    float* stemp = sA + 11652;
    float* sdw   = sA + 11656;

    int bw = blockIdx.x;
    int b  = bw >> 8;
    int wr = (bw >> 4) & 15;
    int wc = bw & 15;
    int tid = threadIdx.x;

    if (tid < 4) stemp[tid] = temp[tid];
    for (int l = tid; l < 900; l += 256) tbl[l] = table[l];
    for (int l = tid; l < 576; l += 256) sdw[l] = wdw[l];

    // t-patch (10x10 per channel) for depthwise
    for (int l = tid; l < 6400; l += 256) {
        int c = l / 100, p = l - c * 100;
        int py = p / 10, px = p - py * 10;
        int gy = wr * 8 - 1 + py, gx = wc * 8 - 1 + px;
        float v = 0.f;
        if ((unsigned)gy < 128u && (unsigned)gx < 128u)
            v = g_t[((size_t)b * 64 + c) * PX + gy * 128 + gx];
        tp[l] = v;
    }
    __syncthreads();

    // depthwise + filt -> vsm
    for (int l = tid; l < 4096; l += 256) {
        int c = l >> 6, n = l & 63;
        int y = n >> 3, x = n & 7;
        const float* tc = tp + c * 100;
        const float* wc9 = sdw + c * 9;
        float a0 = 0.f;
#pragma unroll
        for (int dy = 0; dy < 3; dy++)
#pragma unroll
            for (int dx = 0; dx < 3; dx++)
                a0 = fmaf(wc9[dy * 3 + dx], tc[(y + dy) * 10 + x + dx], a0);
        float ft = g_filt[((size_t)b * 64 + c) * PX + (wr * 8 + y) * 128 + wc * 8 + x];
        vsm[l] = a0 * (1.0f + ft);
    }
    __syncthreads();   // all reads of tp done

    // q (shifted ll) -> qs, overlaying tp
    for (int l = tid; l < 4096; l += 256) {
        int c = l >> 6, n = l & 63;
        int y = n >> 3, x = n & 7;
        int qy = (wr * 8 + y + 4) & 127;
        int qx = (wc * 8 + x + 4) & 127;
        qs[l] = g_ll[((size_t)b * 64 + c) * PX + qy * 128 + qx];
    }
    __syncthreads();

    {
        int h = tid >> 6, n = tid & 63;
        float s = 0.f;
#pragma unroll
        for (int d = 0; d < 16; d++) { float v = qs[(h * 16 + d) * 64 + n]; s += v * v; }
        float r = rsqrtf(s);
        scl[tid] = (s > 1e-24f) ? r : 1e12f;
    }
    __syncthreads();

    int h = tid >> 6, n = tid & 63;
    int yn = n >> 3, xn = n & 7;
    float myscl = scl[tid];
    float tph = stemp[h];

    float qn[16];
#pragma unroll
    for (int d = 0; d < 16; d++) qn[d] = qs[(h * 16 + d) * 64 + n] * myscl;

    // pass 1: max over m (QK recomputed in pass 2)
    float mx = -1e30f;
#pragma unroll
    for (int m4 = 0; m4 < 64; m4 += 4) {
        float4 s = make_float4(0.f, 0.f, 0.f, 0.f);
#pragma unroll
        for (int d = 0; d < 16; d++) {
            float qd = qn[d];
            float4 qv = *(const float4*)&qs[(h * 16 + d) * 64 + m4];
            s.x = fmaf(qd, qv.x, s.x);
            s.y = fmaf(qd, qv.y, s.y);
            s.z = fmaf(qd, qv.z, s.z);
            s.w = fmaf(qd, qv.w, s.w);
        }
        float4 sc = *(const float4*)&scl[(h << 6) + m4];
#pragma unroll
        for (int q = 0; q < 4; q++) {
            int m = m4 + q;
            int ym = m >> 3, xm = m & 7;
            int ridx = (yn - ym + 7) * 15 + (xn - xm + 7);
            float sv = (q == 0 ? s.x : q == 1 ? s.y : q == 2 ? s.z : s.w);
            float scv = (q == 0 ? sc.x : q == 1 ? sc.y : q == 2 ? sc.z : sc.w);
            mx = fmaxf(mx, (sv * scv + tbl[ridx * 4 + h]) * tph);
        }
    }

    // pass 2: recompute, exp, accumulate sum and PV
    float sum = 0.f;
    float o[16];
#pragma unroll
    for (int d = 0; d < 16; d++) o[d] = 0.f;
#pragma unroll
    for (int m4 = 0; m4 < 64; m4 += 4) {
        float4 s = make_float4(0.f, 0.f, 0.f, 0.f);
#pragma unroll
        for (int d = 0; d < 16; d++) {
            float qd = qn[d];
            float4 qv = *(const float4*)&qs[(h * 16 + d) * 64 + m4];
            s.x = fmaf(qd, qv.x, s.x);
            s.y = fmaf(qd, qv.y, s.y);
            s.z = fmaf(qd, qv.z, s.z);
            s.w = fmaf(qd, qv.w, s.w);
        }
        float4 sc = *(const float4*)&scl[(h << 6) + m4];
        float e0, e1, e2, e3;
        {
            int ym = m4 >> 3, xm = m4 & 7;
            int rb = (yn - ym + 7) * 15 + (xn - xm + 7);
            e0 = __expf((s.x * sc.x + tbl[rb * 4 + h]) * tph - mx);
            e1 = __expf((s.y * sc.y + tbl[(rb - 1) * 4 + h]) * tph - mx);
            e2 = __expf((s.z * sc.z + tbl[(rb - 2) * 4 + h]) * tph - mx);
            e3 = __expf((s.w * sc.w + tbl[(rb - 3) * 4 + h]) * tph - mx);
        }
        sum += e0 + e1 + e2 + e3;
#pragma unroll
        for (int d = 0; d < 16; d++) {
            float4 vv = *(const float4*)&vsm[(h * 16 + d) * 64 + m4];
            float od = o[d];
            od = fmaf(vv.x, e0, od);
            od = fmaf(vv.y, e1, od);
            od = fmaf(vv.z, e2, od);
            od = fmaf(vv.w, e3, od);
            o[d] = od;
        }
    }
    float inv = 1.0f / sum;

    int oy = (wr * 8 + yn + 4) & 127;
    int ox = (wc * 8 + xn + 4) & 127;
#pragma unroll
    for (int d = 0; d < 16; d++)
        g_z[((size_t)b * 64 + h * 16 + d) * PX + oy * 128 + ox] = tf32r(o[d] * inv);
}

// ---------------- launcher ---------------------------------------------------
extern "C" void kernel_launch(void* const* d_in, const int* in_sizes, int n_in,
                              void* d_out, int out_size) {
    const float* x           = (const float*)d_in[0];
    const float* temperature = (const float*)d_in[1];
    const float* rel_bias    = (const float*)d_in[2];
    const float* w_high1     = (const float*)d_in[3];
    const float* w_high2     = (const float*)d_in[4];
    const float* w_highout   = (const float*)d_in[5];
    const float* w_qkv       = (const float*)d_in[6];
    const float* w_dwconv    = (const float*)d_in[7];
    const float* w_proj      = (const float*)d_in[8];
    float* out = (float*)d_out;

    static int smem_set = 0;
    if (!smem_set) {
        cudaFuncSetAttribute(k_conv3x3_mma,
            cudaFuncAttributeMaxDynamicSharedMemorySize, 2 * BUF3 * 4);
        cudaFuncSetAttribute(k_conv1x1_pair,
            cudaFuncAttributeMaxDynamicSharedMemorySize, 2 * BUF1 * 4);
        cudaFuncSetAttribute(k_conv1x1_proj,
            cudaFuncAttributeMaxDynamicSharedMemorySize, 2 * BUF1 * 4);
        cudaFuncSetAttribute(k_attn,
            cudaFuncAttributeMaxDynamicSharedMemorySize, ATTN_SMEM_WORDS * 4);
        smem_set = 1;
    }

    int nbDwt  = NSUB / 256;                           // 32768
    int nbPrep = (5 * W3_GROUP + 18432 + 255) / 256;   // 792
    dim3 g3(8, 8, 40);
    dim3 gpair(PX / 256, 16);
    dim3 gproj(PX / 256, 8);
    int dyn3 = 2 * BUF3 * 4;
    int dyn1 = 2 * BUF1 * 4;
    int dynA = ATTN_SMEM_WORDS * 4;

    // 1. DWT + weight prep (merged)
    k_dwt_prepw<<<nbDwt + nbPrep, 256>>>(x, nbDwt, w_high1, w_highout, w_high2, w_qkv, w_proj);
    // 2. all five grouped 3x3 convs (high1 x2 + highout x3), relu, merged
    k_conv3x3_mma<<<g3, 256, dyn3>>>();
    // 3. qkv (-> t) and high2 (-> filt) 1x1 convs, merged launch
    k_conv1x1_pair<<<gpair, 256, dyn1>>>();
    // 4. attention with fused depthwise (roll fused), two-pass softmax -> z
    k_attn<<<2048, 256, dynA>>>(rel_bias, temperature, w_dwconv + 128 * 9);
    // 5. proj 1x1 with fused IDWT -> out
    k_conv1x1_proj<<<gproj, 256, dyn1>>>(out);
}